// round 5
// baseline (speedup 1.0000x reference)
#include <cuda_runtime.h>
#include <cuda_bf16.h>
#include <cstdint>
#include <math.h>

// ---------------- problem constants ----------------
#define TOKENS 4096          // B*S = 2*2048
#define SEQ    2048
#define BATCH  2
#define DMODEL 1024
#define D3     3072
#define FFN    4096
#define NHEAD  16
#define HDIM   64

// ---------------- fp32 scratch ----------------
__device__ float g_qkv    [TOKENS * (size_t)D3];
__device__ float g_attnout[TOKENS * (size_t)DMODEL];
__device__ float g_h1     [TOKENS * (size_t)DMODEL];
__device__ float g_ffn2   [TOKENS * (size_t)DMODEL];

// ---------------- bf16 hi/lo scratch ----------------
__device__ __nv_bfloat16 g_xh   [TOKENS * (size_t)DMODEL];
__device__ __nv_bfloat16 g_xl   [TOKENS * (size_t)DMODEL];
__device__ __nv_bfloat16 g_wqt_h[(size_t)D3 * DMODEL];     // [N][K]
__device__ __nv_bfloat16 g_wqt_l[(size_t)D3 * DMODEL];
__device__ __nv_bfloat16 g_wot_h[(size_t)DMODEL * DMODEL];
__device__ __nv_bfloat16 g_wot_l[(size_t)DMODEL * DMODEL];
__device__ __nv_bfloat16 g_w1t_h[(size_t)FFN * DMODEL];
__device__ __nv_bfloat16 g_w1t_l[(size_t)FFN * DMODEL];
__device__ __nv_bfloat16 g_w2t_h[(size_t)DMODEL * FFN];
__device__ __nv_bfloat16 g_w2t_l[(size_t)DMODEL * FFN];
__device__ __nv_bfloat16 g_attnh[TOKENS * (size_t)DMODEL];
__device__ __nv_bfloat16 g_attnl[TOKENS * (size_t)DMODEL];
__device__ __nv_bfloat16 g_h1h  [TOKENS * (size_t)DMODEL];
__device__ __nv_bfloat16 g_h1l  [TOKENS * (size_t)DMODEL];
__device__ __nv_bfloat16 g_fhh  [TOKENS * (size_t)FFN];
__device__ __nv_bfloat16 g_fhl  [TOKENS * (size_t)FFN];

// =====================================================================
// helpers
// =====================================================================
__device__ __forceinline__ uint32_t smem_u32(const void* p) {
    uint32_t a;
    asm("{ .reg .u64 t; cvta.to.shared.u64 t, %1; cvt.u32.u64 %0, t; }"
        : "=r"(a) : "l"(p));
    return a;
}

__device__ __forceinline__ void ldm_x4(uint32_t* r, uint32_t addr) {
    asm volatile("ldmatrix.sync.aligned.m8n8.x4.shared.b16 {%0,%1,%2,%3}, [%4];"
                 : "=r"(r[0]), "=r"(r[1]), "=r"(r[2]), "=r"(r[3]) : "r"(addr));
}

__device__ __forceinline__ void mma_bf16(float* d, const uint32_t* a,
                                         uint32_t b0, uint32_t b1) {
    asm volatile(
        "mma.sync.aligned.m16n8k16.row.col.f32.bf16.bf16.f32 "
        "{%0,%1,%2,%3},{%4,%5,%6,%7},{%8,%9},{%0,%1,%2,%3};"
        : "+f"(d[0]), "+f"(d[1]), "+f"(d[2]), "+f"(d[3])
        : "r"(a[0]), "r"(a[1]), "r"(a[2]), "r"(a[3]), "r"(b0), "r"(b1));
}

__device__ __forceinline__ uint32_t pack_bf16x2_rn(float a, float b) {
    __nv_bfloat162 t = __floats2bfloat162_rn(a, b);
    return *reinterpret_cast<uint32_t*>(&t);
}

// split pair into truncated-hi bf16x2 and rounded-lo bf16x2
__device__ __forceinline__ void split2(float x, float y,
                                       uint32_t& hi, uint32_t& lo) {
    uint32_t ux = __float_as_uint(x), uy = __float_as_uint(y);
    hi = __byte_perm(ux, uy, 0x7632);
    float rx = x - __uint_as_float(ux & 0xffff0000u);
    float ry = y - __uint_as_float(uy & 0xffff0000u);
    lo = pack_bf16x2_rn(rx, ry);
}

__device__ __forceinline__ void cp16(uint32_t dst, const void* src) {
    asm volatile("cp.async.cg.shared.global [%0], [%1], 16;"
                 :: "r"(dst), "l"(src));
}
#define CP_COMMIT() asm volatile("cp.async.commit_group;" ::: "memory")
#define CP_WAIT0()  asm volatile("cp.async.wait_group 0;" ::: "memory")

// =====================================================================
// split kernels (run once per launch; memory-bound)
// =====================================================================
__global__ __launch_bounds__(256)
void split_plain(const float* __restrict__ src,
                 __nv_bfloat16* __restrict__ dh, __nv_bfloat16* __restrict__ dl)
{
    const int idx = blockIdx.x * 256 + threadIdx.x;     // float4 index
    float4 v = ((const float4*)src)[idx];
    uint32_t h01, l01, h23, l23;
    split2(v.x, v.y, h01, l01);
    split2(v.z, v.w, h23, l23);
    ((uint2*)dh)[idx] = make_uint2(h01, h23);
    ((uint2*)dl)[idx] = make_uint2(l01, l23);
}

// W[K][N] -> Th/Tl[N][K]
__global__ __launch_bounds__(256)
void split_transpose(const float* __restrict__ W,
                     __nv_bfloat16* __restrict__ Th, __nv_bfloat16* __restrict__ Tl,
                     int K, int N)
{
    __shared__ float t[32][33];
    const int bn = blockIdx.x * 32, bk = blockIdx.y * 32;
    const int tx = threadIdx.x & 31, ty = threadIdx.x >> 5;   // 32 x 8
    #pragma unroll
    for (int j = 0; j < 32; j += 8)
        t[ty + j][tx] = W[(size_t)(bk + ty + j) * N + bn + tx];
    __syncthreads();
    #pragma unroll
    for (int j = 0; j < 32; j += 8) {
        float v = t[tx][ty + j];
        uint32_t u = __float_as_uint(v);
        size_t o = (size_t)(bn + ty + j) * K + bk + tx;
        ((uint16_t*)Th)[o] = (uint16_t)(u >> 16);
        float r = v - __uint_as_float(u & 0xffff0000u);
        Tl[o] = __float2bfloat16_rn(r);
    }
}

// =====================================================================
// HMMA GEMM on pre-split bf16 operands.
// A: Ah/Al [M][K] row-major bf16.  B: Bh/Bl [N][K] row-major bf16.
// C fp32, or Ch/Cl bf16 hi/lo (OUTBF16).
// CTA 128x128, BK=32, 8 warps (warp tile 64x32), cp.async double buffer.
// =====================================================================
#define STRB 80                       // bytes per smem row (32 bf16 + pad)
#define TILE_HB (128 * STRB)          // 10240 B per tile
#define BUF_B   (4 * TILE_HB)         // Ah, Al, Bh, Bl = 40960 B
#define GEMM_SMEM (2 * BUF_B)         // 81920 B

template<bool RELU, bool OUTBF16>
__global__ __launch_bounds__(256, 1)
void gemm_bf16(const __nv_bfloat16* __restrict__ Ah,
               const __nv_bfloat16* __restrict__ Al,
               const __nv_bfloat16* __restrict__ Bh,
               const __nv_bfloat16* __restrict__ Bl,
               const float* __restrict__ bias,
               float* __restrict__ C,
               __nv_bfloat16* __restrict__ Ch,
               __nv_bfloat16* __restrict__ Cl,
               int M, int N, int K)
{
    extern __shared__ char smraw[];
    const uint32_t sb = smem_u32(smraw);
    const int tid = threadIdx.x;
    const int l   = tid & 31, w = tid >> 5;
    const int bm  = blockIdx.y * 128, bn = blockIdx.x * 128;
    const int wm  = (w & 1) << 6;
    const int wn  = (w >> 1) << 5;

    const int la = l & 15;
    const int lk = (l >> 4) << 3;
    const int T  = K >> 5;

    float acc[4][4][4];
    #pragma unroll
    for (int i = 0; i < 4; ++i)
        #pragma unroll
        for (int j = 0; j < 4; ++j)
            #pragma unroll
            for (int q = 0; q < 4; ++q) acc[i][j][q] = 0.f;

    auto issue_tile = [&](int t) {
        const int k0 = t << 5;
        const uint32_t base = sb + (t & 1) * BUF_B;
        #pragma unroll
        for (int i = 0; i < 2; ++i) {
            const int c   = tid + (i << 8);     // 0..511
            const int row = c >> 2, kc = c & 3;
            const uint32_t doff = base + (uint32_t)(row * STRB + kc * 16);
            const size_t ga = (size_t)(bm + row) * K + k0 + kc * 8;
            const size_t gb = (size_t)(bn + row) * K + k0 + kc * 8;
            cp16(doff,               Ah + ga);
            cp16(doff + TILE_HB,     Al + ga);
            cp16(doff + 2 * TILE_HB, Bh + gb);
            cp16(doff + 3 * TILE_HB, Bl + gb);
        }
        CP_COMMIT();
    };

    auto compute = [&](int bsel) {
        const uint32_t base = sb + bsel * BUF_B;
        #pragma unroll
        for (int ks = 0; ks < 2; ++ks) {
            uint32_t ah[4][4], al[4][4], bh[2][4], bl[2][4];
            #pragma unroll
            for (int mf = 0; mf < 4; ++mf) {
                uint32_t off = (uint32_t)((wm + mf * 16 + la) * STRB +
                                          (ks * 16 + lk) * 2);
                ldm_x4(ah[mf], base + off);
                ldm_x4(al[mf], base + TILE_HB + off);
            }
            #pragma unroll
            for (int nf2 = 0; nf2 < 2; ++nf2) {
                uint32_t off = (uint32_t)((wn + nf2 * 16 + la) * STRB +
                                          (ks * 16 + lk) * 2);
                ldm_x4(bh[nf2], base + 2 * TILE_HB + off);
                ldm_x4(bl[nf2], base + 3 * TILE_HB + off);
            }
            #pragma unroll
            for (int mf = 0; mf < 4; ++mf)
                #pragma unroll
                for (int nf = 0; nf < 4; ++nf) {
                    const int g = nf >> 1, s = nf & 1;
                    mma_bf16(acc[mf][nf], ah[mf], bh[g][s], bh[g][2 + s]);
                    mma_bf16(acc[mf][nf], ah[mf], bl[g][s], bl[g][2 + s]);
                    mma_bf16(acc[mf][nf], al[mf], bh[g][s], bh[g][2 + s]);
                }
        }
    };

    issue_tile(0);
    for (int t = 0; t < T; ++t) {
        CP_WAIT0();
        __syncthreads();
        if (t + 1 < T) issue_tile(t + 1);
        compute(t & 1);
        __syncthreads();
    }

    // ---------------- epilogue ----------------
    const int g  = l >> 2;
    const int tg = (l & 3) << 1;
    #pragma unroll
    for (int mf = 0; mf < 4; ++mf) {
        const int r0 = bm + wm + mf * 16 + g;
        #pragma unroll
        for (int nf = 0; nf < 4; ++nf) {
            const int c = bn + wn + nf * 8 + tg;
            float2 bv = *(const float2*)&bias[c];
            float v0 = acc[mf][nf][0] + bv.x;
            float v1 = acc[mf][nf][1] + bv.y;
            float v2 = acc[mf][nf][2] + bv.x;
            float v3 = acc[mf][nf][3] + bv.y;
            if (RELU) {
                v0 = fmaxf(v0, 0.f); v1 = fmaxf(v1, 0.f);
                v2 = fmaxf(v2, 0.f); v3 = fmaxf(v3, 0.f);
            }
            if (OUTBF16) {
                uint32_t h01, l01, h23, l23;
                split2(v0, v1, h01, l01);
                split2(v2, v3, h23, l23);
                *(uint32_t*)((char*)Ch + ((size_t)r0 * N + c) * 2)       = h01;
                *(uint32_t*)((char*)Cl + ((size_t)r0 * N + c) * 2)       = l01;
                *(uint32_t*)((char*)Ch + ((size_t)(r0 + 8) * N + c) * 2) = h23;
                *(uint32_t*)((char*)Cl + ((size_t)(r0 + 8) * N + c) * 2) = l23;
            } else {
                *(float2*)&C[(size_t)r0 * N + c]       = make_float2(v0, v1);
                *(float2*)&C[(size_t)(r0 + 8) * N + c] = make_float2(v2, v3);
            }
        }
    }
}

// =====================================================================
// Fused flash-style attention (epilogue emits bf16 hi/lo for O-proj).
// =====================================================================
#define QS_STR 65
#define KS_STR 65
#define VS_STR 68
#define PS_STR 68
#define QS_OFF 0
#define KS_OFF (64 * QS_STR)
#define VS_OFF (2 * 64 * QS_STR)
#define PS_OFF (2 * 64 * QS_STR + 64 * VS_STR)
#define ATTN_SMEM_FLOATS (2 * 64 * QS_STR + 2 * 64 * VS_STR)
#define ATTN_SMEM_BYTES  (ATTN_SMEM_FLOATS * 4)

__global__ __launch_bounds__(256)
void attention_kernel(const float* __restrict__ qkv,
                      __nv_bfloat16* __restrict__ outh,
                      __nv_bfloat16* __restrict__ outl)
{
    extern __shared__ float sm[];
    float* Qs = sm + QS_OFF;
    float* Ks = sm + KS_OFF;
    float* Vs = sm + VS_OFF;
    float* Ps = sm + PS_OFF;

    const int tid = threadIdx.x;
    const int b   = blockIdx.y >> 4;
    const int h   = blockIdx.y & 15;
    const int q0  = blockIdx.x << 6;
    const int tx  = tid & 15;
    const int ty  = tid >> 4;
    const int r0  = ty << 2;
    const int c0  = tx << 2;

    const size_t tokbase = (size_t)b * SEQ;
    const int hoff = h * 192;

    #pragma unroll
    for (int u = 0; u < 4; ++u) {
        int fid = tid + u * 256;
        int r   = fid >> 4;
        int dg  = (fid & 15) << 2;
        float4 v = *(const float4*)&qkv[(tokbase + q0 + r) * D3 + hoff + dg];
        Qs[(dg + 0) * QS_STR + r] = v.x;
        Qs[(dg + 1) * QS_STR + r] = v.y;
        Qs[(dg + 2) * QS_STR + r] = v.z;
        Qs[(dg + 3) * QS_STR + r] = v.w;
    }

    float m[4], lsum[4], o[4][4];
    #pragma unroll
    for (int i = 0; i < 4; ++i) {
        m[i] = -1e30f; lsum[i] = 0.f;
        #pragma unroll
        for (int j = 0; j < 4; ++j) o[i][j] = 0.f;
    }

    for (int kt = 0; kt < SEQ / 64; ++kt) {
        __syncthreads();
        #pragma unroll
        for (int u = 0; u < 4; ++u) {
            int fid = tid + u * 256;
            int r   = fid >> 4;
            int dg  = (fid & 15) << 2;
            size_t gaddr = (tokbase + (size_t)kt * 64 + r) * D3 + hoff;
            float4 kv = *(const float4*)&qkv[gaddr + 64 + dg];
            Ks[(dg + 0) * KS_STR + r] = kv.x;
            Ks[(dg + 1) * KS_STR + r] = kv.y;
            Ks[(dg + 2) * KS_STR + r] = kv.z;
            Ks[(dg + 3) * KS_STR + r] = kv.w;
            float4 vv = *(const float4*)&qkv[gaddr + 128 + dg];
            *(float4*)&Vs[r * VS_STR + dg] = vv;
        }
        __syncthreads();

        float s[4][4] = {};
        #pragma unroll 8
        for (int d = 0; d < 64; ++d) {
            float qv[4], kv[4];
            #pragma unroll
            for (int i = 0; i < 4; ++i) qv[i] = Qs[d * QS_STR + r0 + i];
            #pragma unroll
            for (int j = 0; j < 4; ++j) kv[j] = Ks[d * KS_STR + c0 + j];
            #pragma unroll
            for (int i = 0; i < 4; ++i)
                #pragma unroll
                for (int j = 0; j < 4; ++j)
                    s[i][j] += qv[i] * kv[j];
        }

        #pragma unroll
        for (int i = 0; i < 4; ++i) {
            #pragma unroll
            for (int j = 0; j < 4; ++j) s[i][j] *= 0.125f;
            float rm = fmaxf(fmaxf(s[i][0], s[i][1]), fmaxf(s[i][2], s[i][3]));
            rm = fmaxf(rm, __shfl_xor_sync(0xffffffffu, rm, 1));
            rm = fmaxf(rm, __shfl_xor_sync(0xffffffffu, rm, 2));
            rm = fmaxf(rm, __shfl_xor_sync(0xffffffffu, rm, 4));
            rm = fmaxf(rm, __shfl_xor_sync(0xffffffffu, rm, 8));
            float mn   = fmaxf(m[i], rm);
            float corr = __expf(m[i] - mn);
            float p0 = __expf(s[i][0] - mn);
            float p1 = __expf(s[i][1] - mn);
            float p2 = __expf(s[i][2] - mn);
            float p3 = __expf(s[i][3] - mn);
            *(float4*)&Ps[(r0 + i) * PS_STR + c0] = make_float4(p0, p1, p2, p3);
            float rs = p0 + p1 + p2 + p3;
            rs += __shfl_xor_sync(0xffffffffu, rs, 1);
            rs += __shfl_xor_sync(0xffffffffu, rs, 2);
            rs += __shfl_xor_sync(0xffffffffu, rs, 4);
            rs += __shfl_xor_sync(0xffffffffu, rs, 8);
            lsum[i] = lsum[i] * corr + rs;
            m[i] = mn;
            #pragma unroll
            for (int j = 0; j < 4; ++j) o[i][j] *= corr;
        }
        __syncthreads();

        #pragma unroll 4
        for (int kk = 0; kk < 64; ++kk) {
            float4 v4 = *(float4*)&Vs[kk * VS_STR + c0];
            #pragma unroll
            for (int i = 0; i < 4; ++i) {
                float p = Ps[(r0 + i) * PS_STR + kk];
                o[i][0] += p * v4.x;
                o[i][1] += p * v4.y;
                o[i][2] += p * v4.z;
                o[i][3] += p * v4.w;
            }
        }
    }

    #pragma unroll
    for (int i = 0; i < 4; ++i) {
        float inv = 1.f / lsum[i];
        float v0 = o[i][0] * inv, v1 = o[i][1] * inv;
        float v2 = o[i][2] * inv, v3 = o[i][3] * inv;
        uint32_t h01, l01, h23, l23;
        split2(v0, v1, h01, l01);
        split2(v2, v3, h23, l23);
        const size_t eo = (tokbase + q0 + r0 + i) * DMODEL + h * HDIM + c0;
        *(uint2*)((char*)outh + eo * 2) = make_uint2(h01, h23);
        *(uint2*)((char*)outl + eo * 2) = make_uint2(l01, l23);
    }
}

// =====================================================================
// Fused residual add + LayerNorm; optionally emits bf16 hi/lo too.
// =====================================================================
template<bool EMIT>
__global__ __launch_bounds__(256)
void add_ln_kernel(const float* __restrict__ a, const float* __restrict__ res,
                   const float* __restrict__ gamma, const float* __restrict__ beta,
                   float* __restrict__ out,
                   __nv_bfloat16* __restrict__ outh,
                   __nv_bfloat16* __restrict__ outl)
{
    __shared__ float ss[8], qq[8];
    const int row = blockIdx.x;
    const int tid = threadIdx.x;
    const size_t base = (size_t)row * DMODEL + tid * 4;

    float4 va = *(const float4*)&a[base];
    float4 vr = *(const float4*)&res[base];
    float x0 = va.x + vr.x, x1 = va.y + vr.y, x2 = va.z + vr.z, x3 = va.w + vr.w;

    float s = x0 + x1 + x2 + x3;
    float q = x0 * x0 + x1 * x1 + x2 * x2 + x3 * x3;
    #pragma unroll
    for (int off = 16; off > 0; off >>= 1) {
        s += __shfl_xor_sync(0xffffffffu, s, off);
        q += __shfl_xor_sync(0xffffffffu, q, off);
    }
    const int w = tid >> 5;
    if ((tid & 31) == 0) { ss[w] = s; qq[w] = q; }
    __syncthreads();
    if (tid < 32) {
        float s2 = (tid < 8) ? ss[tid] : 0.f;
        float q2 = (tid < 8) ? qq[tid] : 0.f;
        #pragma unroll
        for (int off = 4; off > 0; off >>= 1) {
            s2 += __shfl_xor_sync(0xffffffffu, s2, off);
            q2 += __shfl_xor_sync(0xffffffffu, q2, off);
        }
        if (tid == 0) { ss[0] = s2; qq[0] = q2; }
    }
    __syncthreads();

    const float mean = ss[0] * (1.f / DMODEL);
    const float var  = qq[0] * (1.f / DMODEL) - mean * mean;
    const float rstd = rsqrtf(var + 1e-5f);

    float4 g  = *(const float4*)&gamma[tid * 4];
    float4 bt = *(const float4*)&beta[tid * 4];
    float4 ov;
    ov.x = (x0 - mean) * rstd * g.x + bt.x;
    ov.y = (x1 - mean) * rstd * g.y + bt.y;
    ov.z = (x2 - mean) * rstd * g.z + bt.z;
    ov.w = (x3 - mean) * rstd * g.w + bt.w;
    *(float4*)&out[base] = ov;

    if (EMIT) {
        uint32_t h01, l01, h23, l23;
        split2(ov.x, ov.y, h01, l01);
        split2(ov.z, ov.w, h23, l23);
        *(uint2*)((char*)outh + base * 2) = make_uint2(h01, h23);
        *(uint2*)((char*)outl + base * 2) = make_uint2(l01, l23);
    }
}

// =====================================================================
// kernel_launch
// =====================================================================
extern "C" void kernel_launch(void* const* d_in, const int* in_sizes, int n_in,
                              void* d_out, int out_size)
{
    const float* x      = (const float*)d_in[0];
    const float* W_qkv  = (const float*)d_in[1];
    const float* b_qkv  = (const float*)d_in[2];
    const float* W_o    = (const float*)d_in[3];
    const float* b_o    = (const float*)d_in[4];
    const float* gamma1 = (const float*)d_in[5];
    const float* beta1  = (const float*)d_in[6];
    const float* W1     = (const float*)d_in[7];
    const float* b1     = (const float*)d_in[8];
    const float* W2     = (const float*)d_in[9];
    const float* b2     = (const float*)d_in[10];
    const float* gamma2 = (const float*)d_in[11];
    const float* beta2  = (const float*)d_in[12];
    float* out = (float*)d_out;

    float *qkv, *attnout, *h1, *ffn2;
    cudaGetSymbolAddress((void**)&qkv,     g_qkv);
    cudaGetSymbolAddress((void**)&attnout, g_attnout);
    cudaGetSymbolAddress((void**)&h1,      g_h1);
    cudaGetSymbolAddress((void**)&ffn2,    g_ffn2);

    __nv_bfloat16 *xh, *xl, *wqh, *wql, *woh, *wol, *w1h, *w1l, *w2h, *w2l;
    __nv_bfloat16 *ath, *atl, *h1h, *h1l, *fhh, *fhl;
    cudaGetSymbolAddress((void**)&xh,  g_xh);   cudaGetSymbolAddress((void**)&xl,  g_xl);
    cudaGetSymbolAddress((void**)&wqh, g_wqt_h);cudaGetSymbolAddress((void**)&wql, g_wqt_l);
    cudaGetSymbolAddress((void**)&woh, g_wot_h);cudaGetSymbolAddress((void**)&wol, g_wot_l);
    cudaGetSymbolAddress((void**)&w1h, g_w1t_h);cudaGetSymbolAddress((void**)&w1l, g_w1t_l);
    cudaGetSymbolAddress((void**)&w2h, g_w2t_h);cudaGetSymbolAddress((void**)&w2l, g_w2t_l);
    cudaGetSymbolAddress((void**)&ath, g_attnh);cudaGetSymbolAddress((void**)&atl, g_attnl);
    cudaGetSymbolAddress((void**)&h1h, g_h1h);  cudaGetSymbolAddress((void**)&h1l, g_h1l);
    cudaGetSymbolAddress((void**)&fhh, g_fhh);  cudaGetSymbolAddress((void**)&fhl, g_fhl);

    cudaFuncSetAttribute(attention_kernel,
                         cudaFuncAttributeMaxDynamicSharedMemorySize,
                         ATTN_SMEM_BYTES);
    cudaFuncSetAttribute(gemm_bf16<false, false>,
                         cudaFuncAttributeMaxDynamicSharedMemorySize, GEMM_SMEM);
    cudaFuncSetAttribute(gemm_bf16<true, true>,
                         cudaFuncAttributeMaxDynamicSharedMemorySize, GEMM_SMEM);

    dim3 blk(256);

    // ---- one-time splits ----
    split_plain<<<(TOKENS * DMODEL) / (256 * 4), blk>>>(x, xh, xl);
    split_transpose<<<dim3(D3 / 32,    DMODEL / 32), blk>>>(W_qkv, wqh, wql, DMODEL, D3);
    split_transpose<<<dim3(DMODEL / 32, DMODEL / 32), blk>>>(W_o,  woh, wol, DMODEL, DMODEL);
    split_transpose<<<dim3(FFN / 32,   DMODEL / 32), blk>>>(W1,   w1h, w1l, DMODEL, FFN);
    split_transpose<<<dim3(DMODEL / 32, FFN / 32),   blk>>>(W2,   w2h, w2l, FFN, DMODEL);

    // 1) qkv = x @ W_qkv + b_qkv                       [4096, 3072]
    gemm_bf16<false, false><<<dim3(D3 / 128, TOKENS / 128), blk, GEMM_SMEM>>>(
        xh, xl, wqh, wql, b_qkv, qkv, nullptr, nullptr, TOKENS, D3, DMODEL);

    // 2) fused attention -> bf16 hi/lo                 [4096, 1024]
    attention_kernel<<<dim3(SEQ / 64, BATCH * NHEAD), blk, ATTN_SMEM_BYTES>>>(
        qkv, ath, atl);

    // 3) attn_out = attn @ W_o + b_o                   [4096, 1024]
    gemm_bf16<false, false><<<dim3(DMODEL / 128, TOKENS / 128), blk, GEMM_SMEM>>>(
        ath, atl, woh, wol, b_o, attnout, nullptr, nullptr, TOKENS, DMODEL, DMODEL);

    // 4) h1 = LN(attn_out + x)  (+ bf16 hi/lo)
    add_ln_kernel<true><<<TOKENS, blk>>>(attnout, x, gamma1, beta1, h1, h1h, h1l);

    // 5) ffnh = relu(h1 @ W1 + b1) -> bf16 hi/lo       [4096, 4096]
    gemm_bf16<true, true><<<dim3(FFN / 128, TOKENS / 128), blk, GEMM_SMEM>>>(
        h1h, h1l, w1h, w1l, b1, nullptr, fhh, fhl, TOKENS, FFN, DMODEL);

    // 6) ffn2 = ffnh @ W2 + b2                         [4096, 1024]
    gemm_bf16<false, false><<<dim3(DMODEL / 128, TOKENS / 128), blk, GEMM_SMEM>>>(
        fhh, fhl, w2h, w2l, b2, ffn2, nullptr, nullptr, TOKENS, DMODEL, FFN);

    // 7) out = LN(ffn2 + h1)
    add_ln_kernel<false><<<TOKENS, blk>>>(ffn2, h1, gamma2, beta2, out,
                                          nullptr, nullptr);
}

// round 6
// speedup vs baseline: 1.1688x; 1.1688x over previous
#include <cuda_runtime.h>
#include <cuda_fp16.h>
#include <cstdint>
#include <math.h>

// ---------------- problem constants ----------------
#define TOKENS 4096          // B*S = 2*2048
#define SEQ    2048
#define BATCH  2
#define DMODEL 1024
#define D3     3072
#define FFN    4096
#define NHEAD  16
#define HDIM   64

// ---------------- fp32 scratch ----------------
__device__ float g_qkv    [TOKENS * (size_t)D3];
__device__ float g_attnout[TOKENS * (size_t)DMODEL];
__device__ float g_h1     [TOKENS * (size_t)DMODEL];
__device__ float g_ffn2   [TOKENS * (size_t)DMODEL];

// ---------------- fp16 hi/lo scratch ----------------
__device__ __half g_xh   [TOKENS * (size_t)DMODEL];
__device__ __half g_xl   [TOKENS * (size_t)DMODEL];
__device__ __half g_wqt_h[(size_t)D3 * DMODEL];     // [N][K]
__device__ __half g_wot_h[(size_t)DMODEL * DMODEL];
__device__ __half g_w1t_h[(size_t)FFN * DMODEL];
__device__ __half g_w2t_h[(size_t)DMODEL * FFN];
__device__ __half g_attnh[TOKENS * (size_t)DMODEL];
__device__ __half g_attnl[TOKENS * (size_t)DMODEL];
__device__ __half g_h1h  [TOKENS * (size_t)DMODEL];
__device__ __half g_h1l  [TOKENS * (size_t)DMODEL];
__device__ __half g_fhh  [TOKENS * (size_t)FFN];
__device__ __half g_fhl  [TOKENS * (size_t)FFN];

// =====================================================================
// helpers
// =====================================================================
__device__ __forceinline__ uint32_t smem_u32(const void* p) {
    uint32_t a;
    asm("{ .reg .u64 t; cvta.to.shared.u64 t, %1; cvt.u32.u64 %0, t; }"
        : "=r"(a) : "l"(p));
    return a;
}

__device__ __forceinline__ void ldm_x4(uint32_t* r, uint32_t addr) {
    asm volatile("ldmatrix.sync.aligned.m8n8.x4.shared.b16 {%0,%1,%2,%3}, [%4];"
                 : "=r"(r[0]), "=r"(r[1]), "=r"(r[2]), "=r"(r[3]) : "r"(addr));
}

__device__ __forceinline__ void mma_f16(float* d, const uint32_t* a,
                                        uint32_t b0, uint32_t b1) {
    asm volatile(
        "mma.sync.aligned.m16n8k16.row.col.f32.f16.f16.f32 "
        "{%0,%1,%2,%3},{%4,%5,%6,%7},{%8,%9},{%0,%1,%2,%3};"
        : "+f"(d[0]), "+f"(d[1]), "+f"(d[2]), "+f"(d[3])
        : "r"(a[0]), "r"(a[1]), "r"(a[2]), "r"(a[3]), "r"(b0), "r"(b1));
}

// split pair into fp16-rn hi pair and fp16-rn residual-lo pair
__device__ __forceinline__ void split2h(float x, float y,
                                        uint32_t& hi, uint32_t& lo) {
    __half2 h = __floats2half2_rn(x, y);
    hi = *reinterpret_cast<uint32_t*>(&h);
    float rx = x - __half2float(__low2half(h));
    float ry = y - __half2float(__high2half(h));
    __half2 l = __floats2half2_rn(rx, ry);
    lo = *reinterpret_cast<uint32_t*>(&l);
}

__device__ __forceinline__ void cp16(uint32_t dst, const void* src) {
    asm volatile("cp.async.cg.shared.global [%0], [%1], 16;"
                 :: "r"(dst), "l"(src));
}
#define CP_COMMIT() asm volatile("cp.async.commit_group;" ::: "memory")
#define CP_WAIT0()  asm volatile("cp.async.wait_group 0;" ::: "memory")

// =====================================================================
// split kernels (run once per launch; memory-bound)
// =====================================================================
__global__ __launch_bounds__(256)
void split_plain(const float* __restrict__ src,
                 __half* __restrict__ dh, __half* __restrict__ dl)
{
    const int idx = blockIdx.x * 256 + threadIdx.x;     // float4 index
    float4 v = ((const float4*)src)[idx];
    uint32_t h01, l01, h23, l23;
    split2h(v.x, v.y, h01, l01);
    split2h(v.z, v.w, h23, l23);
    ((uint2*)dh)[idx] = make_uint2(h01, h23);
    ((uint2*)dl)[idx] = make_uint2(l01, l23);
}

// W[K][N] -> Th[N][K] (fp16-rn, hi only)
__global__ __launch_bounds__(256)
void conv_transpose(const float* __restrict__ W,
                    __half* __restrict__ Th, int K, int N)
{
    __shared__ float t[32][33];
    const int bn = blockIdx.x * 32, bk = blockIdx.y * 32;
    const int tx = threadIdx.x & 31, ty = threadIdx.x >> 5;   // 32 x 8
    #pragma unroll
    for (int j = 0; j < 32; j += 8)
        t[ty + j][tx] = W[(size_t)(bk + ty + j) * N + bn + tx];
    __syncthreads();
    #pragma unroll
    for (int j = 0; j < 32; j += 8) {
        size_t o = (size_t)(bn + ty + j) * K + bk + tx;
        Th[o] = __float2half_rn(t[tx][ty + j]);
    }
}

// =====================================================================
// HMMA GEMM, fp16 2-term: C = (Ah+Al) @ Bh^T + bias.
// A: Ah/Al [M][K] fp16.  B: Bh [N][K] fp16.
// CTA 128x128, BK=32, 8 warps (warp tile 64x32), cp.async double buffer.
// =====================================================================
#define STRB 80                       // bytes per smem row (32 fp16 + pad)
#define TILE_HB (128 * STRB)          // 10240 B per tile
#define BUF_B   (3 * TILE_HB)         // Ah, Al, Bh = 30720 B
#define GEMM_SMEM (2 * BUF_B)         // 61440 B

template<bool RELU, bool OUTF16>
__global__ __launch_bounds__(256, 1)
void gemm_f16(const __half* __restrict__ Ah,
              const __half* __restrict__ Al,
              const __half* __restrict__ Bh,
              const float* __restrict__ bias,
              float* __restrict__ C,
              __half* __restrict__ Ch,
              __half* __restrict__ Cl,
              int M, int N, int K)
{
    extern __shared__ char smraw[];
    const uint32_t sb = smem_u32(smraw);
    const int tid = threadIdx.x;
    const int l   = tid & 31, w = tid >> 5;
    const int bm  = blockIdx.y * 128, bn = blockIdx.x * 128;
    const int wm  = (w & 1) << 6;
    const int wn  = (w >> 1) << 5;

    const int la = l & 15;
    const int lk = (l >> 4) << 3;
    const int T  = K >> 5;

    float acc[4][4][4];
    #pragma unroll
    for (int i = 0; i < 4; ++i)
        #pragma unroll
        for (int j = 0; j < 4; ++j)
            #pragma unroll
            for (int q = 0; q < 4; ++q) acc[i][j][q] = 0.f;

    auto issue_tile = [&](int t) {
        const int k0 = t << 5;
        const uint32_t base = sb + (t & 1) * BUF_B;
        #pragma unroll
        for (int i = 0; i < 2; ++i) {
            const int c   = tid + (i << 8);     // 0..511
            const int row = c >> 2, kc = c & 3;
            const uint32_t doff = base + (uint32_t)(row * STRB + kc * 16);
            const size_t ga = (size_t)(bm + row) * K + k0 + kc * 8;
            const size_t gb = (size_t)(bn + row) * K + k0 + kc * 8;
            cp16(doff,               Ah + ga);
            cp16(doff + TILE_HB,     Al + ga);
            cp16(doff + 2 * TILE_HB, Bh + gb);
        }
        CP_COMMIT();
    };

    auto compute = [&](int bsel) {
        const uint32_t base = sb + bsel * BUF_B;
        #pragma unroll
        for (int ks = 0; ks < 2; ++ks) {
            uint32_t ah[4][4], al[4][4], bh[2][4];
            #pragma unroll
            for (int mf = 0; mf < 4; ++mf) {
                uint32_t off = (uint32_t)((wm + mf * 16 + la) * STRB +
                                          (ks * 16 + lk) * 2);
                ldm_x4(ah[mf], base + off);
                ldm_x4(al[mf], base + TILE_HB + off);
            }
            #pragma unroll
            for (int nf2 = 0; nf2 < 2; ++nf2) {
                uint32_t off = (uint32_t)((wn + nf2 * 16 + la) * STRB +
                                          (ks * 16 + lk) * 2);
                ldm_x4(bh[nf2], base + 2 * TILE_HB + off);
            }
            #pragma unroll
            for (int mf = 0; mf < 4; ++mf)
                #pragma unroll
                for (int nf = 0; nf < 4; ++nf) {
                    const int g = nf >> 1, s = nf & 1;
                    mma_f16(acc[mf][nf], ah[mf], bh[g][s], bh[g][2 + s]);
                    mma_f16(acc[mf][nf], al[mf], bh[g][s], bh[g][2 + s]);
                }
        }
    };

    issue_tile(0);
    for (int t = 0; t < T; ++t) {
        CP_WAIT0();
        __syncthreads();
        if (t + 1 < T) issue_tile(t + 1);
        compute(t & 1);
        __syncthreads();
    }

    // ---------------- epilogue ----------------
    const int g  = l >> 2;
    const int tg = (l & 3) << 1;
    #pragma unroll
    for (int mf = 0; mf < 4; ++mf) {
        const int r0 = bm + wm + mf * 16 + g;
        #pragma unroll
        for (int nf = 0; nf < 4; ++nf) {
            const int c = bn + wn + nf * 8 + tg;
            float2 bv = *(const float2*)&bias[c];
            float v0 = acc[mf][nf][0] + bv.x;
            float v1 = acc[mf][nf][1] + bv.y;
            float v2 = acc[mf][nf][2] + bv.x;
            float v3 = acc[mf][nf][3] + bv.y;
            if (RELU) {
                v0 = fmaxf(v0, 0.f); v1 = fmaxf(v1, 0.f);
                v2 = fmaxf(v2, 0.f); v3 = fmaxf(v3, 0.f);
            }
            if (OUTF16) {
                uint32_t h01, l01, h23, l23;
                split2h(v0, v1, h01, l01);
                split2h(v2, v3, h23, l23);
                *(uint32_t*)((char*)Ch + ((size_t)r0 * N + c) * 2)       = h01;
                *(uint32_t*)((char*)Cl + ((size_t)r0 * N + c) * 2)       = l01;
                *(uint32_t*)((char*)Ch + ((size_t)(r0 + 8) * N + c) * 2) = h23;
                *(uint32_t*)((char*)Cl + ((size_t)(r0 + 8) * N + c) * 2) = l23;
            } else {
                *(float2*)&C[(size_t)r0 * N + c]       = make_float2(v0, v1);
                *(float2*)&C[(size_t)(r0 + 8) * N + c] = make_float2(v2, v3);
            }
        }
    }
}

// =====================================================================
// Fused flash-style attention (epilogue emits fp16 hi/lo for O-proj).
// =====================================================================
#define QS_STR 65
#define KS_STR 65
#define VS_STR 68
#define PS_STR 68
#define QS_OFF 0
#define KS_OFF (64 * QS_STR)
#define VS_OFF (2 * 64 * QS_STR)
#define PS_OFF (2 * 64 * QS_STR + 64 * VS_STR)
#define ATTN_SMEM_FLOATS (2 * 64 * QS_STR + 2 * 64 * VS_STR)
#define ATTN_SMEM_BYTES  (ATTN_SMEM_FLOATS * 4)

__global__ __launch_bounds__(256)
void attention_kernel(const float* __restrict__ qkv,
                      __half* __restrict__ outh,
                      __half* __restrict__ outl)
{
    extern __shared__ float sm[];
    float* Qs = sm + QS_OFF;
    float* Ks = sm + KS_OFF;
    float* Vs = sm + VS_OFF;
    float* Ps = sm + PS_OFF;

    const int tid = threadIdx.x;
    const int b   = blockIdx.y >> 4;
    const int h   = blockIdx.y & 15;
    const int q0  = blockIdx.x << 6;
    const int tx  = tid & 15;
    const int ty  = tid >> 4;
    const int r0  = ty << 2;
    const int c0  = tx << 2;

    const size_t tokbase = (size_t)b * SEQ;
    const int hoff = h * 192;

    #pragma unroll
    for (int u = 0; u < 4; ++u) {
        int fid = tid + u * 256;
        int r   = fid >> 4;
        int dg  = (fid & 15) << 2;
        float4 v = *(const float4*)&qkv[(tokbase + q0 + r) * D3 + hoff + dg];
        Qs[(dg + 0) * QS_STR + r] = v.x;
        Qs[(dg + 1) * QS_STR + r] = v.y;
        Qs[(dg + 2) * QS_STR + r] = v.z;
        Qs[(dg + 3) * QS_STR + r] = v.w;
    }

    float m[4], lsum[4], o[4][4];
    #pragma unroll
    for (int i = 0; i < 4; ++i) {
        m[i] = -1e30f; lsum[i] = 0.f;
        #pragma unroll
        for (int j = 0; j < 4; ++j) o[i][j] = 0.f;
    }

    for (int kt = 0; kt < SEQ / 64; ++kt) {
        __syncthreads();
        #pragma unroll
        for (int u = 0; u < 4; ++u) {
            int fid = tid + u * 256;
            int r   = fid >> 4;
            int dg  = (fid & 15) << 2;
            size_t gaddr = (tokbase + (size_t)kt * 64 + r) * D3 + hoff;
            float4 kv = *(const float4*)&qkv[gaddr + 64 + dg];
            Ks[(dg + 0) * KS_STR + r] = kv.x;
            Ks[(dg + 1) * KS_STR + r] = kv.y;
            Ks[(dg + 2) * KS_STR + r] = kv.z;
            Ks[(dg + 3) * KS_STR + r] = kv.w;
            float4 vv = *(const float4*)&qkv[gaddr + 128 + dg];
            *(float4*)&Vs[r * VS_STR + dg] = vv;
        }
        __syncthreads();

        float s[4][4] = {};
        #pragma unroll 8
        for (int d = 0; d < 64; ++d) {
            float qv[4], kv[4];
            #pragma unroll
            for (int i = 0; i < 4; ++i) qv[i] = Qs[d * QS_STR + r0 + i];
            #pragma unroll
            for (int j = 0; j < 4; ++j) kv[j] = Ks[d * KS_STR + c0 + j];
            #pragma unroll
            for (int i = 0; i < 4; ++i)
                #pragma unroll
                for (int j = 0; j < 4; ++j)
                    s[i][j] += qv[i] * kv[j];
        }

        #pragma unroll
        for (int i = 0; i < 4; ++i) {
            #pragma unroll
            for (int j = 0; j < 4; ++j) s[i][j] *= 0.125f;
            float rm = fmaxf(fmaxf(s[i][0], s[i][1]), fmaxf(s[i][2], s[i][3]));
            rm = fmaxf(rm, __shfl_xor_sync(0xffffffffu, rm, 1));
            rm = fmaxf(rm, __shfl_xor_sync(0xffffffffu, rm, 2));
            rm = fmaxf(rm, __shfl_xor_sync(0xffffffffu, rm, 4));
            rm = fmaxf(rm, __shfl_xor_sync(0xffffffffu, rm, 8));
            float mn   = fmaxf(m[i], rm);
            float corr = __expf(m[i] - mn);
            float p0 = __expf(s[i][0] - mn);
            float p1 = __expf(s[i][1] - mn);
            float p2 = __expf(s[i][2] - mn);
            float p3 = __expf(s[i][3] - mn);
            *(float4*)&Ps[(r0 + i) * PS_STR + c0] = make_float4(p0, p1, p2, p3);
            float rs = p0 + p1 + p2 + p3;
            rs += __shfl_xor_sync(0xffffffffu, rs, 1);
            rs += __shfl_xor_sync(0xffffffffu, rs, 2);
            rs += __shfl_xor_sync(0xffffffffu, rs, 4);
            rs += __shfl_xor_sync(0xffffffffu, rs, 8);
            lsum[i] = lsum[i] * corr + rs;
            m[i] = mn;
            #pragma unroll
            for (int j = 0; j < 4; ++j) o[i][j] *= corr;
        }
        __syncthreads();

        #pragma unroll 4
        for (int kk = 0; kk < 64; ++kk) {
            float4 v4 = *(float4*)&Vs[kk * VS_STR + c0];
            #pragma unroll
            for (int i = 0; i < 4; ++i) {
                float p = Ps[(r0 + i) * PS_STR + kk];
                o[i][0] += p * v4.x;
                o[i][1] += p * v4.y;
                o[i][2] += p * v4.z;
                o[i][3] += p * v4.w;
            }
        }
    }

    #pragma unroll
    for (int i = 0; i < 4; ++i) {
        float inv = 1.f / lsum[i];
        float v0 = o[i][0] * inv, v1 = o[i][1] * inv;
        float v2 = o[i][2] * inv, v3 = o[i][3] * inv;
        uint32_t h01, l01, h23, l23;
        split2h(v0, v1, h01, l01);
        split2h(v2, v3, h23, l23);
        const size_t eo = (tokbase + q0 + r0 + i) * DMODEL + h * HDIM + c0;
        *(uint2*)((char*)outh + eo * 2) = make_uint2(h01, h23);
        *(uint2*)((char*)outl + eo * 2) = make_uint2(l01, l23);
    }
}

// =====================================================================
// Fused residual add + LayerNorm; optionally emits fp16 hi/lo too.
// =====================================================================
template<bool EMIT>
__global__ __launch_bounds__(256)
void add_ln_kernel(const float* __restrict__ a, const float* __restrict__ res,
                   const float* __restrict__ gamma, const float* __restrict__ beta,
                   float* __restrict__ out,
                   __half* __restrict__ outh,
                   __half* __restrict__ outl)
{
    __shared__ float ss[8], qq[8];
    const int row = blockIdx.x;
    const int tid = threadIdx.x;
    const size_t base = (size_t)row * DMODEL + tid * 4;

    float4 va = *(const float4*)&a[base];
    float4 vr = *(const float4*)&res[base];
    float x0 = va.x + vr.x, x1 = va.y + vr.y, x2 = va.z + vr.z, x3 = va.w + vr.w;

    float s = x0 + x1 + x2 + x3;
    float q = x0 * x0 + x1 * x1 + x2 * x2 + x3 * x3;
    #pragma unroll
    for (int off = 16; off > 0; off >>= 1) {
        s += __shfl_xor_sync(0xffffffffu, s, off);
        q += __shfl_xor_sync(0xffffffffu, q, off);
    }
    const int w = tid >> 5;
    if ((tid & 31) == 0) { ss[w] = s; qq[w] = q; }
    __syncthreads();
    if (tid < 32) {
        float s2 = (tid < 8) ? ss[tid] : 0.f;
        float q2 = (tid < 8) ? qq[tid] : 0.f;
        #pragma unroll
        for (int off = 4; off > 0; off >>= 1) {
            s2 += __shfl_xor_sync(0xffffffffu, s2, off);
            q2 += __shfl_xor_sync(0xffffffffu, q2, off);
        }
        if (tid == 0) { ss[0] = s2; qq[0] = q2; }
    }
    __syncthreads();

    const float mean = ss[0] * (1.f / DMODEL);
    const float var  = qq[0] * (1.f / DMODEL) - mean * mean;
    const float rstd = rsqrtf(var + 1e-5f);

    float4 g  = *(const float4*)&gamma[tid * 4];
    float4 bt = *(const float4*)&beta[tid * 4];
    float4 ov;
    ov.x = (x0 - mean) * rstd * g.x + bt.x;
    ov.y = (x1 - mean) * rstd * g.y + bt.y;
    ov.z = (x2 - mean) * rstd * g.z + bt.z;
    ov.w = (x3 - mean) * rstd * g.w + bt.w;
    *(float4*)&out[base] = ov;

    if (EMIT) {
        uint32_t h01, l01, h23, l23;
        split2h(ov.x, ov.y, h01, l01);
        split2h(ov.z, ov.w, h23, l23);
        *(uint2*)((char*)outh + base * 2) = make_uint2(h01, h23);
        *(uint2*)((char*)outl + base * 2) = make_uint2(l01, l23);
    }
}

// =====================================================================
// kernel_launch
// =====================================================================
extern "C" void kernel_launch(void* const* d_in, const int* in_sizes, int n_in,
                              void* d_out, int out_size)
{
    const float* x      = (const float*)d_in[0];
    const float* W_qkv  = (const float*)d_in[1];
    const float* b_qkv  = (const float*)d_in[2];
    const float* W_o    = (const float*)d_in[3];
    const float* b_o    = (const float*)d_in[4];
    const float* gamma1 = (const float*)d_in[5];
    const float* beta1  = (const float*)d_in[6];
    const float* W1     = (const float*)d_in[7];
    const float* b1     = (const float*)d_in[8];
    const float* W2     = (const float*)d_in[9];
    const float* b2     = (const float*)d_in[10];
    const float* gamma2 = (const float*)d_in[11];
    const float* beta2  = (const float*)d_in[12];
    float* out = (float*)d_out;

    float *qkv, *attnout, *h1, *ffn2;
    cudaGetSymbolAddress((void**)&qkv,     g_qkv);
    cudaGetSymbolAddress((void**)&attnout, g_attnout);
    cudaGetSymbolAddress((void**)&h1,      g_h1);
    cudaGetSymbolAddress((void**)&ffn2,    g_ffn2);

    __half *xh, *xl, *wqh, *woh, *w1h, *w2h;
    __half *ath, *atl, *h1h, *h1l, *fhh, *fhl;
    cudaGetSymbolAddress((void**)&xh,  g_xh);   cudaGetSymbolAddress((void**)&xl,  g_xl);
    cudaGetSymbolAddress((void**)&wqh, g_wqt_h);
    cudaGetSymbolAddress((void**)&woh, g_wot_h);
    cudaGetSymbolAddress((void**)&w1h, g_w1t_h);
    cudaGetSymbolAddress((void**)&w2h, g_w2t_h);
    cudaGetSymbolAddress((void**)&ath, g_attnh);cudaGetSymbolAddress((void**)&atl, g_attnl);
    cudaGetSymbolAddress((void**)&h1h, g_h1h);  cudaGetSymbolAddress((void**)&h1l, g_h1l);
    cudaGetSymbolAddress((void**)&fhh, g_fhh);  cudaGetSymbolAddress((void**)&fhl, g_fhl);

    cudaFuncSetAttribute(attention_kernel,
                         cudaFuncAttributeMaxDynamicSharedMemorySize,
                         ATTN_SMEM_BYTES);
    cudaFuncSetAttribute(gemm_f16<false, false>,
                         cudaFuncAttributeMaxDynamicSharedMemorySize, GEMM_SMEM);
    cudaFuncSetAttribute(gemm_f16<true, true>,
                         cudaFuncAttributeMaxDynamicSharedMemorySize, GEMM_SMEM);

    dim3 blk(256);

    // ---- one-time converts/splits ----
    split_plain<<<(TOKENS * DMODEL) / (256 * 4), blk>>>(x, xh, xl);
    conv_transpose<<<dim3(D3 / 32,    DMODEL / 32), blk>>>(W_qkv, wqh, DMODEL, D3);
    conv_transpose<<<dim3(DMODEL / 32, DMODEL / 32), blk>>>(W_o,  woh, DMODEL, DMODEL);
    conv_transpose<<<dim3(FFN / 32,   DMODEL / 32), blk>>>(W1,   w1h, DMODEL, FFN);
    conv_transpose<<<dim3(DMODEL / 32, FFN / 32),   blk>>>(W2,   w2h, FFN, DMODEL);

    // 1) qkv = x @ W_qkv + b_qkv                       [4096, 3072]
    gemm_f16<false, false><<<dim3(D3 / 128, TOKENS / 128), blk, GEMM_SMEM>>>(
        xh, xl, wqh, b_qkv, qkv, nullptr, nullptr, TOKENS, D3, DMODEL);

    // 2) fused attention -> fp16 hi/lo                 [4096, 1024]
    attention_kernel<<<dim3(SEQ / 64, BATCH * NHEAD), blk, ATTN_SMEM_BYTES>>>(
        qkv, ath, atl);

    // 3) attn_out = attn @ W_o + b_o                   [4096, 1024]
    gemm_f16<false, false><<<dim3(DMODEL / 128, TOKENS / 128), blk, GEMM_SMEM>>>(
        ath, atl, woh, b_o, attnout, nullptr, nullptr, TOKENS, DMODEL, DMODEL);

    // 4) h1 = LN(attn_out + x)  (+ fp16 hi/lo)
    add_ln_kernel<true><<<TOKENS, blk>>>(attnout, x, gamma1, beta1, h1, h1h, h1l);

    // 5) ffnh = relu(h1 @ W1 + b1) -> fp16 hi/lo       [4096, 4096]
    gemm_f16<true, true><<<dim3(FFN / 128, TOKENS / 128), blk, GEMM_SMEM>>>(
        h1h, h1l, w1h, b1, nullptr, fhh, fhl, TOKENS, FFN, DMODEL);

    // 6) ffn2 = ffnh @ W2 + b2                         [4096, 1024]
    gemm_f16<false, false><<<dim3(DMODEL / 128, TOKENS / 128), blk, GEMM_SMEM>>>(
        fhh, fhl, w2h, b2, ffn2, nullptr, nullptr, TOKENS, DMODEL, FFN);

    // 7) out = LN(ffn2 + h1)
    add_ln_kernel<false><<<TOKENS, blk>>>(ffn2, h1, gamma2, beta2, out,
                                          nullptr, nullptr);
}

// round 7
// speedup vs baseline: 1.9899x; 1.7026x over previous
#include <cuda_runtime.h>
#include <cuda_fp16.h>
#include <cstdint>
#include <math.h>

// ---------------- problem constants ----------------
#define TOKENS 4096          // B*S = 2*2048
#define SEQ    2048
#define BATCH  2
#define DMODEL 1024
#define D3     3072
#define FFN    4096
#define NHEAD  16
#define HDIM   64

// ---------------- fp32 scratch ----------------
__device__ float g_qkv    [TOKENS * (size_t)D3];
__device__ float g_attnout[TOKENS * (size_t)DMODEL];
__device__ float g_h1     [TOKENS * (size_t)DMODEL];
__device__ float g_ffn2   [TOKENS * (size_t)DMODEL];

// ---------------- fp16 hi/lo scratch ----------------
__device__ __half g_xh   [TOKENS * (size_t)DMODEL];
__device__ __half g_xl   [TOKENS * (size_t)DMODEL];
__device__ __half g_wqt_h[(size_t)D3 * DMODEL];     // [N][K]
__device__ __half g_wot_h[(size_t)DMODEL * DMODEL];
__device__ __half g_w1t_h[(size_t)FFN * DMODEL];
__device__ __half g_w2t_h[(size_t)DMODEL * FFN];
__device__ __half g_attnh[TOKENS * (size_t)DMODEL];
__device__ __half g_attnl[TOKENS * (size_t)DMODEL];
__device__ __half g_h1h  [TOKENS * (size_t)DMODEL];
__device__ __half g_h1l  [TOKENS * (size_t)DMODEL];
__device__ __half g_fhh  [TOKENS * (size_t)FFN];
__device__ __half g_fhl  [TOKENS * (size_t)FFN];

// ---------------- per-head planar fp16 QKV (for MMA attention) ----------
// layout: [bh][seq][64]
__device__ __half g_qph[(size_t)BATCH * NHEAD * SEQ * HDIM];
__device__ __half g_qpl[(size_t)BATCH * NHEAD * SEQ * HDIM];
__device__ __half g_kph[(size_t)BATCH * NHEAD * SEQ * HDIM];
__device__ __half g_vph[(size_t)BATCH * NHEAD * SEQ * HDIM];
__device__ __half g_vpl[(size_t)BATCH * NHEAD * SEQ * HDIM];

// =====================================================================
// helpers
// =====================================================================
__device__ __forceinline__ uint32_t smem_u32(const void* p) {
    uint32_t a;
    asm("{ .reg .u64 t; cvta.to.shared.u64 t, %1; cvt.u32.u64 %0, t; }"
        : "=r"(a) : "l"(p));
    return a;
}

__device__ __forceinline__ void ldm_x4(uint32_t* r, uint32_t addr) {
    asm volatile("ldmatrix.sync.aligned.m8n8.x4.shared.b16 {%0,%1,%2,%3}, [%4];"
                 : "=r"(r[0]), "=r"(r[1]), "=r"(r[2]), "=r"(r[3]) : "r"(addr));
}

__device__ __forceinline__ void ldm_x4t(uint32_t* r, uint32_t addr) {
    asm volatile("ldmatrix.sync.aligned.m8n8.x4.trans.shared.b16 {%0,%1,%2,%3}, [%4];"
                 : "=r"(r[0]), "=r"(r[1]), "=r"(r[2]), "=r"(r[3]) : "r"(addr));
}

__device__ __forceinline__ void mma_f16(float* d, const uint32_t* a,
                                        uint32_t b0, uint32_t b1) {
    asm volatile(
        "mma.sync.aligned.m16n8k16.row.col.f32.f16.f16.f32 "
        "{%0,%1,%2,%3},{%4,%5,%6,%7},{%8,%9},{%0,%1,%2,%3};"
        : "+f"(d[0]), "+f"(d[1]), "+f"(d[2]), "+f"(d[3])
        : "r"(a[0]), "r"(a[1]), "r"(a[2]), "r"(a[3]), "r"(b0), "r"(b1));
}

__device__ __forceinline__ uint32_t packh2(float a, float b) {
    __half2 h = __floats2half2_rn(a, b);
    return *reinterpret_cast<uint32_t*>(&h);
}

// split pair into fp16-rn hi pair and fp16-rn residual-lo pair
__device__ __forceinline__ void split2h(float x, float y,
                                        uint32_t& hi, uint32_t& lo) {
    __half2 h = __floats2half2_rn(x, y);
    hi = *reinterpret_cast<uint32_t*>(&h);
    float rx = x - __half2float(__low2half(h));
    float ry = y - __half2float(__high2half(h));
    __half2 l = __floats2half2_rn(rx, ry);
    lo = *reinterpret_cast<uint32_t*>(&l);
}

__device__ __forceinline__ void cp16(uint32_t dst, const void* src) {
    asm volatile("cp.async.cg.shared.global [%0], [%1], 16;"
                 :: "r"(dst), "l"(src));
}
#define CP_COMMIT() asm volatile("cp.async.commit_group;" ::: "memory")
#define CP_WAIT0()  asm volatile("cp.async.wait_group 0;" ::: "memory")

// =====================================================================
// split kernels (run once per launch; memory-bound)
// =====================================================================
__global__ __launch_bounds__(256)
void split_plain(const float* __restrict__ src,
                 __half* __restrict__ dh, __half* __restrict__ dl)
{
    const int idx = blockIdx.x * 256 + threadIdx.x;     // float4 index
    float4 v = ((const float4*)src)[idx];
    uint32_t h01, l01, h23, l23;
    split2h(v.x, v.y, h01, l01);
    split2h(v.z, v.w, h23, l23);
    ((uint2*)dh)[idx] = make_uint2(h01, h23);
    ((uint2*)dl)[idx] = make_uint2(l01, l23);
}

// W[K][N] -> Th[N][K] (fp16-rn, hi only)
__global__ __launch_bounds__(256)
void conv_transpose(const float* __restrict__ W,
                    __half* __restrict__ Th, int K, int N)
{
    __shared__ float t[32][33];
    const int bn = blockIdx.x * 32, bk = blockIdx.y * 32;
    const int tx = threadIdx.x & 31, ty = threadIdx.x >> 5;   // 32 x 8
    #pragma unroll
    for (int j = 0; j < 32; j += 8)
        t[ty + j][tx] = W[(size_t)(bk + ty + j) * N + bn + tx];
    __syncthreads();
    #pragma unroll
    for (int j = 0; j < 32; j += 8) {
        size_t o = (size_t)(bn + ty + j) * K + bk + tx;
        Th[o] = __float2half_rn(t[tx][ty + j]);
    }
}

// qkv fp32 [token][3072] -> per-head planar fp16.
// Q pre-scaled by 0.125 (1/sqrt(64)) and split hi/lo; K hi; V hi/lo.
__global__ __launch_bounds__(256)
void split_qkv(const float* __restrict__ qkv,
               __half* __restrict__ qh, __half* __restrict__ ql,
               __half* __restrict__ kh,
               __half* __restrict__ vh, __half* __restrict__ vl)
{
    const int idx = blockIdx.x * 256 + threadIdx.x;   // float4 index over [4096][768]
    const int token = idx / 768;
    const int r     = idx % 768;
    const int h     = r / 48;
    const int r2    = r % 48;
    const int part  = r2 / 16;        // 0=q 1=k 2=v
    const int d4    = r2 % 16;

    float4 v = ((const float4*)qkv)[idx];
    const int b = token >> 11, s = token & 2047;
    const size_t po = (((size_t)(b * 16 + h) * SEQ + s) * HDIM + d4 * 4);

    if (part == 0) {
        uint32_t h01, l01, h23, l23;
        split2h(v.x * 0.125f, v.y * 0.125f, h01, l01);
        split2h(v.z * 0.125f, v.w * 0.125f, h23, l23);
        *(uint2*)(qh + po) = make_uint2(h01, h23);
        *(uint2*)(ql + po) = make_uint2(l01, l23);
    } else if (part == 1) {
        *(uint2*)(kh + po) = make_uint2(packh2(v.x, v.y), packh2(v.z, v.w));
    } else {
        uint32_t h01, l01, h23, l23;
        split2h(v.x, v.y, h01, l01);
        split2h(v.z, v.w, h23, l23);
        *(uint2*)(vh + po) = make_uint2(h01, h23);
        *(uint2*)(vl + po) = make_uint2(l01, l23);
    }
}

// =====================================================================
// HMMA GEMM, fp16 2-term: C = (Ah+Al) @ Bh^T + bias.  (unchanged, proven)
// =====================================================================
#define STRB 80                       // bytes per smem row (32 fp16 + pad)
#define TILE_HB (128 * STRB)          // 10240 B per tile
#define BUF_B   (3 * TILE_HB)         // Ah, Al, Bh = 30720 B
#define GEMM_SMEM (2 * BUF_B)         // 61440 B

template<bool RELU, bool OUTF16>
__global__ __launch_bounds__(256, 1)
void gemm_f16(const __half* __restrict__ Ah,
              const __half* __restrict__ Al,
              const __half* __restrict__ Bh,
              const float* __restrict__ bias,
              float* __restrict__ C,
              __half* __restrict__ Ch,
              __half* __restrict__ Cl,
              int M, int N, int K)
{
    extern __shared__ char smraw[];
    const uint32_t sb = smem_u32(smraw);
    const int tid = threadIdx.x;
    const int l   = tid & 31, w = tid >> 5;
    const int bm  = blockIdx.y * 128, bn = blockIdx.x * 128;
    const int wm  = (w & 1) << 6;
    const int wn  = (w >> 1) << 5;

    const int la = l & 15;
    const int lk = (l >> 4) << 3;
    const int T  = K >> 5;

    float acc[4][4][4];
    #pragma unroll
    for (int i = 0; i < 4; ++i)
        #pragma unroll
        for (int j = 0; j < 4; ++j)
            #pragma unroll
            for (int q = 0; q < 4; ++q) acc[i][j][q] = 0.f;

    auto issue_tile = [&](int t) {
        const int k0 = t << 5;
        const uint32_t base = sb + (t & 1) * BUF_B;
        #pragma unroll
        for (int i = 0; i < 2; ++i) {
            const int c   = tid + (i << 8);     // 0..511
            const int row = c >> 2, kc = c & 3;
            const uint32_t doff = base + (uint32_t)(row * STRB + kc * 16);
            const size_t ga = (size_t)(bm + row) * K + k0 + kc * 8;
            const size_t gb = (size_t)(bn + row) * K + k0 + kc * 8;
            cp16(doff,               Ah + ga);
            cp16(doff + TILE_HB,     Al + ga);
            cp16(doff + 2 * TILE_HB, Bh + gb);
        }
        CP_COMMIT();
    };

    auto compute = [&](int bsel) {
        const uint32_t base = sb + bsel * BUF_B;
        #pragma unroll
        for (int ks = 0; ks < 2; ++ks) {
            uint32_t ah[4][4], al[4][4], bh[2][4];
            #pragma unroll
            for (int mf = 0; mf < 4; ++mf) {
                uint32_t off = (uint32_t)((wm + mf * 16 + la) * STRB +
                                          (ks * 16 + lk) * 2);
                ldm_x4(ah[mf], base + off);
                ldm_x4(al[mf], base + TILE_HB + off);
            }
            #pragma unroll
            for (int nf2 = 0; nf2 < 2; ++nf2) {
                uint32_t off = (uint32_t)((wn + nf2 * 16 + la) * STRB +
                                          (ks * 16 + lk) * 2);
                ldm_x4(bh[nf2], base + 2 * TILE_HB + off);
            }
            #pragma unroll
            for (int mf = 0; mf < 4; ++mf)
                #pragma unroll
                for (int nf = 0; nf < 4; ++nf) {
                    const int g = nf >> 1, s = nf & 1;
                    mma_f16(acc[mf][nf], ah[mf], bh[g][s], bh[g][2 + s]);
                    mma_f16(acc[mf][nf], al[mf], bh[g][s], bh[g][2 + s]);
                }
        }
    };

    issue_tile(0);
    for (int t = 0; t < T; ++t) {
        CP_WAIT0();
        __syncthreads();
        if (t + 1 < T) issue_tile(t + 1);
        compute(t & 1);
        __syncthreads();
    }

    const int g  = l >> 2;
    const int tg = (l & 3) << 1;
    #pragma unroll
    for (int mf = 0; mf < 4; ++mf) {
        const int r0 = bm + wm + mf * 16 + g;
        #pragma unroll
        for (int nf = 0; nf < 4; ++nf) {
            const int c = bn + wn + nf * 8 + tg;
            float2 bv = *(const float2*)&bias[c];
            float v0 = acc[mf][nf][0] + bv.x;
            float v1 = acc[mf][nf][1] + bv.y;
            float v2 = acc[mf][nf][2] + bv.x;
            float v3 = acc[mf][nf][3] + bv.y;
            if (RELU) {
                v0 = fmaxf(v0, 0.f); v1 = fmaxf(v1, 0.f);
                v2 = fmaxf(v2, 0.f); v3 = fmaxf(v3, 0.f);
            }
            if (OUTF16) {
                uint32_t h01, l01, h23, l23;
                split2h(v0, v1, h01, l01);
                split2h(v2, v3, h23, l23);
                *(uint32_t*)((char*)Ch + ((size_t)r0 * N + c) * 2)       = h01;
                *(uint32_t*)((char*)Cl + ((size_t)r0 * N + c) * 2)       = l01;
                *(uint32_t*)((char*)Ch + ((size_t)(r0 + 8) * N + c) * 2) = h23;
                *(uint32_t*)((char*)Cl + ((size_t)(r0 + 8) * N + c) * 2) = l23;
            } else {
                *(float2*)&C[(size_t)r0 * N + c]       = make_float2(v0, v1);
                *(float2*)&C[(size_t)(r0 + 8) * N + c] = make_float2(v2, v3);
            }
        }
    }
}

// =====================================================================
// MMA flash attention.
// grid (16 qtiles, 32 bh), 256 threads (8 warps), warp = 16 q-rows.
// Q tile 128x64 (hi/lo), K tile 128x64 (hi), V tile 128x64 (hi/lo),
// K/V cp.async double-buffered.  Output: fp16 hi/lo [token][1024].
// =====================================================================
#define A_STR   72                         // halves per smem row (64 + 8 pad)
#define A_TILE  (128 * A_STR)              // 9216 halves per tile
#define A_QH    0
#define A_QL    A_TILE
#define A_BUF0  (2 * A_TILE)               // 18432
#define A_BUFSZ (3 * A_TILE)               // Kh, Vh, Vl = 27648 halves
#define A_KH    0
#define A_VH    A_TILE
#define A_VL    (2 * A_TILE)
#define ATTN_SMEM ((A_BUF0 + 2 * A_BUFSZ) * 2)   // 147456 bytes

__global__ __launch_bounds__(256, 1)
void attention_mma(const __half* __restrict__ qh_g, const __half* __restrict__ ql_g,
                   const __half* __restrict__ kh_g,
                   const __half* __restrict__ vh_g, const __half* __restrict__ vl_g,
                   __half* __restrict__ outh, __half* __restrict__ outl)
{
    extern __shared__ char smraw[];
    const uint32_t sb = smem_u32(smraw);
    const int tid = threadIdx.x;
    const int l   = tid & 31, w = tid >> 5;
    const int qt  = blockIdx.x;
    const int bh  = blockIdx.y;
    const int b   = bh >> 4, h = bh & 15;

    const size_t plane = (size_t)bh * SEQ * HDIM;
    const int la  = l & 15;
    const int lk8 = (l >> 4) << 3;
    const int qrow0 = w << 4;

    auto load_tile = [&](const __half* src, uint32_t dsth, int row0) {
        #pragma unroll
        for (int i = 0; i < 4; ++i) {
            const int c   = tid + (i << 8);        // 0..1023
            const int row = c >> 3, c8 = (c & 7) << 3;
            cp16(sb + (dsth + row * A_STR + c8) * 2,
                 src + plane + (size_t)(row0 + row) * HDIM + c8);
        }
    };

    // prologue: Q (once) + K/V tile 0
    load_tile(qh_g, A_QH, qt * 128);
    load_tile(ql_g, A_QL, qt * 128);
    load_tile(kh_g, A_BUF0 + A_KH, 0);
    load_tile(vh_g, A_BUF0 + A_VH, 0);
    load_tile(vl_g, A_BUF0 + A_VL, 0);
    CP_COMMIT();

    float oacc[8][4];
    #pragma unroll
    for (int i = 0; i < 8; ++i)
        #pragma unroll
        for (int j = 0; j < 4; ++j) oacc[i][j] = 0.f;
    float mrow0 = -1e30f, mrow1 = -1e30f, lrow0 = 0.f, lrow1 = 0.f;

    for (int kt = 0; kt < SEQ / 128; ++kt) {
        CP_WAIT0();
        __syncthreads();
        if (kt + 1 < SEQ / 128) {
            const uint32_t nb = A_BUF0 + ((kt + 1) & 1) * A_BUFSZ;
            load_tile(kh_g, nb + A_KH, (kt + 1) * 128);
            load_tile(vh_g, nb + A_VH, (kt + 1) * 128);
            load_tile(vl_g, nb + A_VL, (kt + 1) * 128);
            CP_COMMIT();
        }
        const uint32_t kb_base = sb + (A_BUF0 + (kt & 1) * A_BUFSZ) * 2;

        // ---- S = Q K^T (128 cols) ----
        float sacc[16][4];
        #pragma unroll
        for (int i = 0; i < 16; ++i)
            #pragma unroll
            for (int j = 0; j < 4; ++j) sacc[i][j] = 0.f;

        #pragma unroll
        for (int ks = 0; ks < 4; ++ks) {
            const uint32_t qoff = (uint32_t)((qrow0 + la) * A_STR + ks * 16 + lk8) * 2;
            uint32_t qhf[4], qlf[4];
            ldm_x4(qhf, sb + A_QH * 2 + qoff);
            ldm_x4(qlf, sb + A_QL * 2 + qoff);
            uint32_t kb[8][4];
            #pragma unroll
            for (int g2 = 0; g2 < 8; ++g2)
                ldm_x4(kb[g2], kb_base +
                       (uint32_t)(((g2 << 4) + la) * A_STR + ks * 16 + lk8) * 2);
            #pragma unroll
            for (int nf = 0; nf < 16; ++nf) {
                const int g2 = nf >> 1, s = nf & 1;
                mma_f16(sacc[nf], qhf, kb[g2][s], kb[g2][2 + s]);
                mma_f16(sacc[nf], qlf, kb[g2][s], kb[g2][2 + s]);
            }
        }

        // ---- online softmax (scores already scaled via Q) ----
        float tm0 = -1e30f, tm1 = -1e30f;
        #pragma unroll
        for (int nf = 0; nf < 16; ++nf) {
            tm0 = fmaxf(tm0, fmaxf(sacc[nf][0], sacc[nf][1]));
            tm1 = fmaxf(tm1, fmaxf(sacc[nf][2], sacc[nf][3]));
        }
        tm0 = fmaxf(tm0, __shfl_xor_sync(0xffffffffu, tm0, 1));
        tm0 = fmaxf(tm0, __shfl_xor_sync(0xffffffffu, tm0, 2));
        tm1 = fmaxf(tm1, __shfl_xor_sync(0xffffffffu, tm1, 1));
        tm1 = fmaxf(tm1, __shfl_xor_sync(0xffffffffu, tm1, 2));
        const float m0n = fmaxf(mrow0, tm0), m1n = fmaxf(mrow1, tm1);
        const float c0 = __expf(mrow0 - m0n), c1 = __expf(mrow1 - m1n);
        float rs0 = 0.f, rs1 = 0.f;
        #pragma unroll
        for (int nf = 0; nf < 16; ++nf) {
            sacc[nf][0] = __expf(sacc[nf][0] - m0n);
            sacc[nf][1] = __expf(sacc[nf][1] - m0n);
            sacc[nf][2] = __expf(sacc[nf][2] - m1n);
            sacc[nf][3] = __expf(sacc[nf][3] - m1n);
            rs0 += sacc[nf][0] + sacc[nf][1];
            rs1 += sacc[nf][2] + sacc[nf][3];
        }
        rs0 += __shfl_xor_sync(0xffffffffu, rs0, 1);
        rs0 += __shfl_xor_sync(0xffffffffu, rs0, 2);
        rs1 += __shfl_xor_sync(0xffffffffu, rs1, 1);
        rs1 += __shfl_xor_sync(0xffffffffu, rs1, 2);
        lrow0 = lrow0 * c0 + rs0;  mrow0 = m0n;
        lrow1 = lrow1 * c1 + rs1;  mrow1 = m1n;
        #pragma unroll
        for (int nf = 0; nf < 8; ++nf) {
            oacc[nf][0] *= c0; oacc[nf][1] *= c0;
            oacc[nf][2] *= c1; oacc[nf][3] *= c1;
        }

        // ---- O += P V  (P from registers; V hi/lo via ldmatrix.trans) ----
        #pragma unroll
        for (int ks2 = 0; ks2 < 8; ++ks2) {
            uint32_t aP[4];
            aP[0] = packh2(sacc[2 * ks2][0],     sacc[2 * ks2][1]);
            aP[1] = packh2(sacc[2 * ks2][2],     sacc[2 * ks2][3]);
            aP[2] = packh2(sacc[2 * ks2 + 1][0], sacc[2 * ks2 + 1][1]);
            aP[3] = packh2(sacc[2 * ks2 + 1][2], sacc[2 * ks2 + 1][3]);
            #pragma unroll
            for (int nb = 0; nb < 4; ++nb) {
                const uint32_t voff =
                    (uint32_t)(((ks2 << 4) + la) * A_STR + (nb << 4) + lk8) * 2;
                uint32_t vbh[4], vbl[4];
                ldm_x4t(vbh, kb_base + A_VH * 2 + voff);
                ldm_x4t(vbl, kb_base + A_VL * 2 + voff);
                mma_f16(oacc[2 * nb],     aP, vbh[0], vbh[1]);
                mma_f16(oacc[2 * nb + 1], aP, vbh[2], vbh[3]);
                mma_f16(oacc[2 * nb],     aP, vbl[0], vbl[1]);
                mma_f16(oacc[2 * nb + 1], aP, vbl[2], vbl[3]);
            }
        }
    }

    // ---- epilogue: normalize + fp16 hi/lo store ----
    const int g  = l >> 2;
    const int tq = (l & 3) << 1;
    const float inv0 = 1.f / lrow0, inv1 = 1.f / lrow1;
    const size_t tok0 = (size_t)b * SEQ + qt * 128 + qrow0 + g;
    #pragma unroll
    for (int nf = 0; nf < 8; ++nf) {
        const int col = h * HDIM + nf * 8 + tq;
        uint32_t h01, l01, h23, l23;
        split2h(oacc[nf][0] * inv0, oacc[nf][1] * inv0, h01, l01);
        split2h(oacc[nf][2] * inv1, oacc[nf][3] * inv1, h23, l23);
        *(uint32_t*)((char*)outh + (tok0 * DMODEL + col) * 2)       = h01;
        *(uint32_t*)((char*)outl + (tok0 * DMODEL + col) * 2)       = l01;
        *(uint32_t*)((char*)outh + ((tok0 + 8) * DMODEL + col) * 2) = h23;
        *(uint32_t*)((char*)outl + ((tok0 + 8) * DMODEL + col) * 2) = l23;
    }
}

// =====================================================================
// Fused residual add + LayerNorm; optionally emits fp16 hi/lo too.
// =====================================================================
template<bool EMIT>
__global__ __launch_bounds__(256)
void add_ln_kernel(const float* __restrict__ a, const float* __restrict__ res,
                   const float* __restrict__ gamma, const float* __restrict__ beta,
                   float* __restrict__ out,
                   __half* __restrict__ outh,
                   __half* __restrict__ outl)
{
    __shared__ float ss[8], qq[8];
    const int row = blockIdx.x;
    const int tid = threadIdx.x;
    const size_t base = (size_t)row * DMODEL + tid * 4;

    float4 va = *(const float4*)&a[base];
    float4 vr = *(const float4*)&res[base];
    float x0 = va.x + vr.x, x1 = va.y + vr.y, x2 = va.z + vr.z, x3 = va.w + vr.w;

    float s = x0 + x1 + x2 + x3;
    float q = x0 * x0 + x1 * x1 + x2 * x2 + x3 * x3;
    #pragma unroll
    for (int off = 16; off > 0; off >>= 1) {
        s += __shfl_xor_sync(0xffffffffu, s, off);
        q += __shfl_xor_sync(0xffffffffu, q, off);
    }
    const int w = tid >> 5;
    if ((tid & 31) == 0) { ss[w] = s; qq[w] = q; }
    __syncthreads();
    if (tid < 32) {
        float s2 = (tid < 8) ? ss[tid] : 0.f;
        float q2 = (tid < 8) ? qq[tid] : 0.f;
        #pragma unroll
        for (int off = 4; off > 0; off >>= 1) {
            s2 += __shfl_xor_sync(0xffffffffu, s2, off);
            q2 += __shfl_xor_sync(0xffffffffu, q2, off);
        }
        if (tid == 0) { ss[0] = s2; qq[0] = q2; }
    }
    __syncthreads();

    const float mean = ss[0] * (1.f / DMODEL);
    const float var  = qq[0] * (1.f / DMODEL) - mean * mean;
    const float rstd = rsqrtf(var + 1e-5f);

    float4 g  = *(const float4*)&gamma[tid * 4];
    float4 bt = *(const float4*)&beta[tid * 4];
    float4 ov;
    ov.x = (x0 - mean) * rstd * g.x + bt.x;
    ov.y = (x1 - mean) * rstd * g.y + bt.y;
    ov.z = (x2 - mean) * rstd * g.z + bt.z;
    ov.w = (x3 - mean) * rstd * g.w + bt.w;
    *(float4*)&out[base] = ov;

    if (EMIT) {
        uint32_t h01, l01, h23, l23;
        split2h(ov.x, ov.y, h01, l01);
        split2h(ov.z, ov.w, h23, l23);
        *(uint2*)((char*)outh + base * 2) = make_uint2(h01, h23);
        *(uint2*)((char*)outl + base * 2) = make_uint2(l01, l23);
    }
}

// =====================================================================
// kernel_launch
// =====================================================================
extern "C" void kernel_launch(void* const* d_in, const int* in_sizes, int n_in,
                              void* d_out, int out_size)
{
    const float* x      = (const float*)d_in[0];
    const float* W_qkv  = (const float*)d_in[1];
    const float* b_qkv  = (const float*)d_in[2];
    const float* W_o    = (const float*)d_in[3];
    const float* b_o    = (const float*)d_in[4];
    const float* gamma1 = (const float*)d_in[5];
    const float* beta1  = (const float*)d_in[6];
    const float* W1     = (const float*)d_in[7];
    const float* b1     = (const float*)d_in[8];
    const float* W2     = (const float*)d_in[9];
    const float* b2     = (const float*)d_in[10];
    const float* gamma2 = (const float*)d_in[11];
    const float* beta2  = (const float*)d_in[12];
    float* out = (float*)d_out;

    float *qkv, *attnout, *h1, *ffn2;
    cudaGetSymbolAddress((void**)&qkv,     g_qkv);
    cudaGetSymbolAddress((void**)&attnout, g_attnout);
    cudaGetSymbolAddress((void**)&h1,      g_h1);
    cudaGetSymbolAddress((void**)&ffn2,    g_ffn2);

    __half *xh, *xl, *wqh, *woh, *w1h, *w2h;
    __half *ath, *atl, *h1h, *h1l, *fhh, *fhl;
    __half *qph, *qpl, *kph, *vph, *vpl;
    cudaGetSymbolAddress((void**)&xh,  g_xh);   cudaGetSymbolAddress((void**)&xl,  g_xl);
    cudaGetSymbolAddress((void**)&wqh, g_wqt_h);
    cudaGetSymbolAddress((void**)&woh, g_wot_h);
    cudaGetSymbolAddress((void**)&w1h, g_w1t_h);
    cudaGetSymbolAddress((void**)&w2h, g_w2t_h);
    cudaGetSymbolAddress((void**)&ath, g_attnh);cudaGetSymbolAddress((void**)&atl, g_attnl);
    cudaGetSymbolAddress((void**)&h1h, g_h1h);  cudaGetSymbolAddress((void**)&h1l, g_h1l);
    cudaGetSymbolAddress((void**)&fhh, g_fhh);  cudaGetSymbolAddress((void**)&fhl, g_fhl);
    cudaGetSymbolAddress((void**)&qph, g_qph);  cudaGetSymbolAddress((void**)&qpl, g_qpl);
    cudaGetSymbolAddress((void**)&kph, g_kph);
    cudaGetSymbolAddress((void**)&vph, g_vph);  cudaGetSymbolAddress((void**)&vpl, g_vpl);

    cudaFuncSetAttribute(attention_mma,
                         cudaFuncAttributeMaxDynamicSharedMemorySize, ATTN_SMEM);
    cudaFuncSetAttribute(gemm_f16<false, false>,
                         cudaFuncAttributeMaxDynamicSharedMemorySize, GEMM_SMEM);
    cudaFuncSetAttribute(gemm_f16<true, true>,
                         cudaFuncAttributeMaxDynamicSharedMemorySize, GEMM_SMEM);

    dim3 blk(256);

    // ---- one-time converts/splits ----
    split_plain<<<(TOKENS * DMODEL) / (256 * 4), blk>>>(x, xh, xl);
    conv_transpose<<<dim3(D3 / 32,    DMODEL / 32), blk>>>(W_qkv, wqh, DMODEL, D3);
    conv_transpose<<<dim3(DMODEL / 32, DMODEL / 32), blk>>>(W_o,  woh, DMODEL, DMODEL);
    conv_transpose<<<dim3(FFN / 32,   DMODEL / 32), blk>>>(W1,   w1h, DMODEL, FFN);
    conv_transpose<<<dim3(DMODEL / 32, FFN / 32),   blk>>>(W2,   w2h, FFN, DMODEL);

    // 1) qkv = x @ W_qkv + b_qkv                       [4096, 3072]
    gemm_f16<false, false><<<dim3(D3 / 128, TOKENS / 128), blk, GEMM_SMEM>>>(
        xh, xl, wqh, b_qkv, qkv, nullptr, nullptr, TOKENS, D3, DMODEL);

    // 1b) split qkv -> per-head planar fp16 (Q pre-scaled)
    split_qkv<<<(TOKENS * D3) / (256 * 4), blk>>>(qkv, qph, qpl, kph, vph, vpl);

    // 2) MMA flash attention -> fp16 hi/lo             [4096, 1024]
    attention_mma<<<dim3(SEQ / 128, BATCH * NHEAD), blk, ATTN_SMEM>>>(
        qph, qpl, kph, vph, vpl, ath, atl);

    // 3) attn_out = attn @ W_o + b_o                   [4096, 1024]
    gemm_f16<false, false><<<dim3(DMODEL / 128, TOKENS / 128), blk, GEMM_SMEM>>>(
        ath, atl, woh, b_o, attnout, nullptr, nullptr, TOKENS, DMODEL, DMODEL);

    // 4) h1 = LN(attn_out + x)  (+ fp16 hi/lo)
    add_ln_kernel<true><<<TOKENS, blk>>>(attnout, x, gamma1, beta1, h1, h1h, h1l);

    // 5) ffnh = relu(h1 @ W1 + b1) -> fp16 hi/lo       [4096, 4096]
    gemm_f16<true, true><<<dim3(FFN / 128, TOKENS / 128), blk, GEMM_SMEM>>>(
        h1h, h1l, w1h, b1, nullptr, fhh, fhl, TOKENS, FFN, DMODEL);

    // 6) ffn2 = ffnh @ W2 + b2                         [4096, 1024]
    gemm_f16<false, false><<<dim3(DMODEL / 128, TOKENS / 128), blk, GEMM_SMEM>>>(
        fhh, fhl, w2h, b2, ffn2, nullptr, nullptr, TOKENS, DMODEL, FFN);

    // 7) out = LN(ffn2 + h1)
    add_ln_kernel<false><<<TOKENS, blk>>>(ffn2, h1, gamma2, beta2, out,
                                          nullptr, nullptr);
}

// round 9
// speedup vs baseline: 3.0811x; 1.5483x over previous
#include <cuda_runtime.h>
#include <cuda_fp16.h>
#include <cstdint>
#include <math.h>

// ---------------- problem constants ----------------
#define TOKENS 4096          // B*S = 2*2048
#define SEQ    2048
#define BATCH  2
#define DMODEL 1024
#define D3     3072
#define FFN    4096
#define NHEAD  16
#define HDIM   64

// ---------------- fp32 scratch ----------------
__device__ float g_qkv    [TOKENS * (size_t)D3];
__device__ float g_attnout[TOKENS * (size_t)DMODEL];
__device__ float g_h1     [TOKENS * (size_t)DMODEL];
__device__ float g_ffn2   [TOKENS * (size_t)DMODEL];

// ---------------- fp16 scratch ----------------
__device__ __half g_xh   [TOKENS * (size_t)DMODEL];
__device__ __half g_wqt_h[(size_t)D3 * DMODEL];     // [N][K]
__device__ __half g_wot_h[(size_t)DMODEL * DMODEL];
__device__ __half g_w1t_h[(size_t)FFN * DMODEL];
__device__ __half g_w2t_h[(size_t)DMODEL * FFN];
__device__ __half g_attnh[TOKENS * (size_t)DMODEL];
__device__ __half g_h1h  [TOKENS * (size_t)DMODEL];
__device__ __half g_fhh  [TOKENS * (size_t)FFN];

// ---------------- per-head planar fp16 QKV (for MMA attention) ----------
// layout: [bh][seq][64]
__device__ __half g_qph[(size_t)BATCH * NHEAD * SEQ * HDIM];
__device__ __half g_qpl[(size_t)BATCH * NHEAD * SEQ * HDIM];
__device__ __half g_kph[(size_t)BATCH * NHEAD * SEQ * HDIM];
__device__ __half g_vph[(size_t)BATCH * NHEAD * SEQ * HDIM];
__device__ __half g_vpl[(size_t)BATCH * NHEAD * SEQ * HDIM];

// =====================================================================
// helpers
// =====================================================================
__device__ __forceinline__ uint32_t smem_u32(const void* p) {
    uint32_t a;
    asm("{ .reg .u64 t; cvta.to.shared.u64 t, %1; cvt.u32.u64 %0, t; }"
        : "=r"(a) : "l"(p));
    return a;
}

__device__ __forceinline__ void ldm_x4(uint32_t* r, uint32_t addr) {
    asm volatile("ldmatrix.sync.aligned.m8n8.x4.shared.b16 {%0,%1,%2,%3}, [%4];"
                 : "=r"(r[0]), "=r"(r[1]), "=r"(r[2]), "=r"(r[3]) : "r"(addr));
}

__device__ __forceinline__ void ldm_x4t(uint32_t* r, uint32_t addr) {
    asm volatile("ldmatrix.sync.aligned.m8n8.x4.trans.shared.b16 {%0,%1,%2,%3}, [%4];"
                 : "=r"(r[0]), "=r"(r[1]), "=r"(r[2]), "=r"(r[3]) : "r"(addr));
}

__device__ __forceinline__ void mma_f16(float* d, const uint32_t* a,
                                        uint32_t b0, uint32_t b1) {
    asm volatile(
        "mma.sync.aligned.m16n8k16.row.col.f32.f16.f16.f32 "
        "{%0,%1,%2,%3},{%4,%5,%6,%7},{%8,%9},{%0,%1,%2,%3};"
        : "+f"(d[0]), "+f"(d[1]), "+f"(d[2]), "+f"(d[3])
        : "r"(a[0]), "r"(a[1]), "r"(a[2]), "r"(a[3]), "r"(b0), "r"(b1));
}

__device__ __forceinline__ uint32_t packh2(float a, float b) {
    __half2 h = __floats2half2_rn(a, b);
    return *reinterpret_cast<uint32_t*>(&h);
}

// split pair into fp16-rn hi pair and fp16-rn residual-lo pair
__device__ __forceinline__ void split2h(float x, float y,
                                        uint32_t& hi, uint32_t& lo) {
    __half2 h = __floats2half2_rn(x, y);
    hi = *reinterpret_cast<uint32_t*>(&h);
    float rx = x - __half2float(__low2half(h));
    float ry = y - __half2float(__high2half(h));
    __half2 l = __floats2half2_rn(rx, ry);
    lo = *reinterpret_cast<uint32_t*>(&l);
}

__device__ __forceinline__ void cp16(uint32_t dst, const void* src) {
    asm volatile("cp.async.cg.shared.global [%0], [%1], 16;"
                 :: "r"(dst), "l"(src));
}
#define CP_COMMIT() asm volatile("cp.async.commit_group;" ::: "memory")
#define CP_WAIT0()  asm volatile("cp.async.wait_group 0;" ::: "memory")

// =====================================================================
// convert kernels (run once per launch; memory-bound)
// =====================================================================
__global__ __launch_bounds__(256)
void conv_plain(const float* __restrict__ src, __half* __restrict__ dh)
{
    const int idx = blockIdx.x * 256 + threadIdx.x;     // float4 index
    float4 v = ((const float4*)src)[idx];
    ((uint2*)dh)[idx] = make_uint2(packh2(v.x, v.y), packh2(v.z, v.w));
}

// W[K][N] -> Th[N][K] (fp16-rn)
__global__ __launch_bounds__(256)
void conv_transpose(const float* __restrict__ W,
                    __half* __restrict__ Th, int K, int N)
{
    __shared__ float t[32][33];
    const int bn = blockIdx.x * 32, bk = blockIdx.y * 32;
    const int tx = threadIdx.x & 31, ty = threadIdx.x >> 5;   // 32 x 8
    #pragma unroll
    for (int j = 0; j < 32; j += 8)
        t[ty + j][tx] = W[(size_t)(bk + ty + j) * N + bn + tx];
    __syncthreads();
    #pragma unroll
    for (int j = 0; j < 32; j += 8) {
        size_t o = (size_t)(bn + ty + j) * K + bk + tx;
        Th[o] = __float2half_rn(t[tx][ty + j]);
    }
}

// qkv fp32 [token][3072] -> per-head planar fp16.
// Q pre-scaled by 0.125 (1/sqrt(64)) and split hi/lo; K hi; V hi/lo.
__global__ __launch_bounds__(256)
void split_qkv(const float* __restrict__ qkv,
               __half* __restrict__ qh, __half* __restrict__ ql,
               __half* __restrict__ kh,
               __half* __restrict__ vh, __half* __restrict__ vl)
{
    const int idx = blockIdx.x * 256 + threadIdx.x;   // float4 index over [4096][768]
    const int token = idx / 768;
    const int r     = idx % 768;
    const int h     = r / 48;
    const int r2    = r % 48;
    const int part  = r2 / 16;        // 0=q 1=k 2=v
    const int d4    = r2 % 16;

    float4 v = ((const float4*)qkv)[idx];
    const int b = token >> 11, s = token & 2047;
    const size_t po = (((size_t)(b * 16 + h) * SEQ + s) * HDIM + d4 * 4);

    if (part == 0) {
        uint32_t h01, l01, h23, l23;
        split2h(v.x * 0.125f, v.y * 0.125f, h01, l01);
        split2h(v.z * 0.125f, v.w * 0.125f, h23, l23);
        *(uint2*)(qh + po) = make_uint2(h01, h23);
        *(uint2*)(ql + po) = make_uint2(l01, l23);
    } else if (part == 1) {
        *(uint2*)(kh + po) = make_uint2(packh2(v.x, v.y), packh2(v.z, v.w));
    } else {
        uint32_t h01, l01, h23, l23;
        split2h(v.x, v.y, h01, l01);
        split2h(v.z, v.w, h23, l23);
        *(uint2*)(vh + po) = make_uint2(h01, h23);
        *(uint2*)(vl + po) = make_uint2(l01, l23);
    }
}

// =====================================================================
// HMMA GEMM, pure fp16: C = A @ B^T + bias.
// A: [M][K] fp16.  B: [N][K] fp16.
// CTA 128x128, BK=32, 8 warps (warp tile 64x32), cp.async double buffer.
// 2 CTAs/SM for latency hiding.
// =====================================================================
#define STRB 80                       // bytes per smem row (32 fp16 + pad)
#define TILE_HB (128 * STRB)          // 10240 B per tile
#define BUF_B   (2 * TILE_HB)         // A, B = 20480 B
#define GEMM_SMEM (2 * BUF_B)         // 40960 B

template<bool RELU, bool OUTF16>
__global__ __launch_bounds__(256, 2)
void gemm_f16(const __half* __restrict__ Ah,
              const __half* __restrict__ Bh,
              const float* __restrict__ bias,
              float* __restrict__ C,
              __half* __restrict__ Ch,
              int M, int N, int K)
{
    extern __shared__ char smraw[];
    const uint32_t sb = smem_u32(smraw);
    const int tid = threadIdx.x;
    const int l   = tid & 31, w = tid >> 5;
    const int bm  = blockIdx.y * 128, bn = blockIdx.x * 128;
    const int wm  = (w & 1) << 6;
    const int wn  = (w >> 1) << 5;

    const int la = l & 15;
    const int lk = (l >> 4) << 3;
    const int T  = K >> 5;

    float acc[4][4][4];
    #pragma unroll
    for (int i = 0; i < 4; ++i)
        #pragma unroll
        for (int j = 0; j < 4; ++j)
            #pragma unroll
            for (int q = 0; q < 4; ++q) acc[i][j][q] = 0.f;

    auto issue_tile = [&](int t) {
        const int k0 = t << 5;
        const uint32_t base = sb + (t & 1) * BUF_B;
        #pragma unroll
        for (int i = 0; i < 2; ++i) {
            const int c   = tid + (i << 8);     // 0..511
            const int row = c >> 2, kc = c & 3;
            const uint32_t doff = base + (uint32_t)(row * STRB + kc * 16);
            cp16(doff,           Ah + (size_t)(bm + row) * K + k0 + kc * 8);
            cp16(doff + TILE_HB, Bh + (size_t)(bn + row) * K + k0 + kc * 8);
        }
        CP_COMMIT();
    };

    auto compute = [&](int bsel) {
        const uint32_t base = sb + bsel * BUF_B;
        #pragma unroll
        for (int ks = 0; ks < 2; ++ks) {
            uint32_t ah[4][4], bh[2][4];
            #pragma unroll
            for (int mf = 0; mf < 4; ++mf) {
                uint32_t off = (uint32_t)((wm + mf * 16 + la) * STRB +
                                          (ks * 16 + lk) * 2);
                ldm_x4(ah[mf], base + off);
            }
            #pragma unroll
            for (int nf2 = 0; nf2 < 2; ++nf2) {
                uint32_t off = (uint32_t)((wn + nf2 * 16 + la) * STRB +
                                          (ks * 16 + lk) * 2);
                ldm_x4(bh[nf2], base + TILE_HB + off);
            }
            #pragma unroll
            for (int mf = 0; mf < 4; ++mf)
                #pragma unroll
                for (int nf = 0; nf < 4; ++nf) {
                    const int g = nf >> 1, s = nf & 1;
                    mma_f16(acc[mf][nf], ah[mf], bh[g][s], bh[g][2 + s]);
                }
        }
    };

    issue_tile(0);
    for (int t = 0; t < T; ++t) {
        CP_WAIT0();
        __syncthreads();
        if (t + 1 < T) issue_tile(t + 1);
        compute(t & 1);
        __syncthreads();
    }

    const int g  = l >> 2;
    const int tg = (l & 3) << 1;
    #pragma unroll
    for (int mf = 0; mf < 4; ++mf) {
        const int r0 = bm + wm + mf * 16 + g;
        #pragma unroll
        for (int nf = 0; nf < 4; ++nf) {
            const int c = bn + wn + nf * 8 + tg;
            float2 bv = *(const float2*)&bias[c];
            float v0 = acc[mf][nf][0] + bv.x;
            float v1 = acc[mf][nf][1] + bv.y;
            float v2 = acc[mf][nf][2] + bv.x;
            float v3 = acc[mf][nf][3] + bv.y;
            if (RELU) {
                v0 = fmaxf(v0, 0.f); v1 = fmaxf(v1, 0.f);
                v2 = fmaxf(v2, 0.f); v3 = fmaxf(v3, 0.f);
            }
            if (OUTF16) {
                *(uint32_t*)((char*)Ch + ((size_t)r0 * N + c) * 2)       = packh2(v0, v1);
                *(uint32_t*)((char*)Ch + ((size_t)(r0 + 8) * N + c) * 2) = packh2(v2, v3);
            } else {
                *(float2*)&C[(size_t)r0 * N + c]       = make_float2(v0, v1);
                *(float2*)&C[(size_t)(r0 + 8) * N + c] = make_float2(v2, v3);
            }
        }
    }
}

// =====================================================================
// MMA flash attention (proven in R7; output now fp16 hi only).
// grid (16 qtiles, 32 bh), 256 threads (8 warps), warp = 16 q-rows.
// =====================================================================
#define A_STR   72                         // halves per smem row (64 + 8 pad)
#define A_TILE  (128 * A_STR)              // 9216 halves per tile
#define A_QH    0
#define A_QL    A_TILE
#define A_BUF0  (2 * A_TILE)               // 18432
#define A_BUFSZ (3 * A_TILE)               // Kh, Vh, Vl = 27648 halves
#define A_KH    0
#define A_VH    A_TILE
#define A_VL    (2 * A_TILE)
#define ATTN_SMEM ((A_BUF0 + 2 * A_BUFSZ) * 2)   // 147456 bytes

__global__ __launch_bounds__(256, 1)
void attention_mma(const __half* __restrict__ qh_g, const __half* __restrict__ ql_g,
                   const __half* __restrict__ kh_g,
                   const __half* __restrict__ vh_g, const __half* __restrict__ vl_g,
                   __half* __restrict__ outh)
{
    extern __shared__ char smraw[];
    const uint32_t sb = smem_u32(smraw);
    const int tid = threadIdx.x;
    const int l   = tid & 31, w = tid >> 5;
    const int qt  = blockIdx.x;
    const int bh  = blockIdx.y;
    const int b   = bh >> 4, h = bh & 15;

    const size_t plane = (size_t)bh * SEQ * HDIM;
    const int la  = l & 15;
    const int lk8 = (l >> 4) << 3;
    const int qrow0 = w << 4;

    auto load_tile = [&](const __half* src, uint32_t dsth, int row0) {
        #pragma unroll
        for (int i = 0; i < 4; ++i) {
            const int c   = tid + (i << 8);        // 0..1023
            const int row = c >> 3, c8 = (c & 7) << 3;
            cp16(sb + (dsth + row * A_STR + c8) * 2,
                 src + plane + (size_t)(row0 + row) * HDIM + c8);
        }
    };

    load_tile(qh_g, A_QH, qt * 128);
    load_tile(ql_g, A_QL, qt * 128);
    load_tile(kh_g, A_BUF0 + A_KH, 0);
    load_tile(vh_g, A_BUF0 + A_VH, 0);
    load_tile(vl_g, A_BUF0 + A_VL, 0);
    CP_COMMIT();

    float oacc[8][4];
    #pragma unroll
    for (int i = 0; i < 8; ++i)
        #pragma unroll
        for (int j = 0; j < 4; ++j) oacc[i][j] = 0.f;
    float mrow0 = -1e30f, mrow1 = -1e30f, lrow0 = 0.f, lrow1 = 0.f;

    for (int kt = 0; kt < SEQ / 128; ++kt) {
        CP_WAIT0();
        __syncthreads();
        if (kt + 1 < SEQ / 128) {
            const uint32_t nb = A_BUF0 + ((kt + 1) & 1) * A_BUFSZ;
            load_tile(kh_g, nb + A_KH, (kt + 1) * 128);
            load_tile(vh_g, nb + A_VH, (kt + 1) * 128);
            load_tile(vl_g, nb + A_VL, (kt + 1) * 128);
            CP_COMMIT();
        }
        const uint32_t kb_base = sb + (A_BUF0 + (kt & 1) * A_BUFSZ) * 2;

        float sacc[16][4];
        #pragma unroll
        for (int i = 0; i < 16; ++i)
            #pragma unroll
            for (int j = 0; j < 4; ++j) sacc[i][j] = 0.f;

        #pragma unroll
        for (int ks = 0; ks < 4; ++ks) {
            const uint32_t qoff = (uint32_t)((qrow0 + la) * A_STR + ks * 16 + lk8) * 2;
            uint32_t qhf[4], qlf[4];
            ldm_x4(qhf, sb + A_QH * 2 + qoff);
            ldm_x4(qlf, sb + A_QL * 2 + qoff);
            uint32_t kb[8][4];
            #pragma unroll
            for (int g2 = 0; g2 < 8; ++g2)
                ldm_x4(kb[g2], kb_base +
                       (uint32_t)(((g2 << 4) + la) * A_STR + ks * 16 + lk8) * 2);
            #pragma unroll
            for (int nf = 0; nf < 16; ++nf) {
                const int g2 = nf >> 1, s = nf & 1;
                mma_f16(sacc[nf], qhf, kb[g2][s], kb[g2][2 + s]);
                mma_f16(sacc[nf], qlf, kb[g2][s], kb[g2][2 + s]);
            }
        }

        float tm0 = -1e30f, tm1 = -1e30f;
        #pragma unroll
        for (int nf = 0; nf < 16; ++nf) {
            tm0 = fmaxf(tm0, fmaxf(sacc[nf][0], sacc[nf][1]));
            tm1 = fmaxf(tm1, fmaxf(sacc[nf][2], sacc[nf][3]));
        }
        tm0 = fmaxf(tm0, __shfl_xor_sync(0xffffffffu, tm0, 1));
        tm0 = fmaxf(tm0, __shfl_xor_sync(0xffffffffu, tm0, 2));
        tm1 = fmaxf(tm1, __shfl_xor_sync(0xffffffffu, tm1, 1));
        tm1 = fmaxf(tm1, __shfl_xor_sync(0xffffffffu, tm1, 2));
        const float m0n = fmaxf(mrow0, tm0), m1n = fmaxf(mrow1, tm1);
        const float c0 = __expf(mrow0 - m0n), c1 = __expf(mrow1 - m1n);
        float rs0 = 0.f, rs1 = 0.f;
        #pragma unroll
        for (int nf = 0; nf < 16; ++nf) {
            sacc[nf][0] = __expf(sacc[nf][0] - m0n);
            sacc[nf][1] = __expf(sacc[nf][1] - m0n);
            sacc[nf][2] = __expf(sacc[nf][2] - m1n);
            sacc[nf][3] = __expf(sacc[nf][3] - m1n);
            rs0 += sacc[nf][0] + sacc[nf][1];
            rs1 += sacc[nf][2] + sacc[nf][3];
        }
        rs0 += __shfl_xor_sync(0xffffffffu, rs0, 1);
        rs0 += __shfl_xor_sync(0xffffffffu, rs0, 2);
        rs1 += __shfl_xor_sync(0xffffffffu, rs1, 1);
        rs1 += __shfl_xor_sync(0xffffffffu, rs1, 2);
        lrow0 = lrow0 * c0 + rs0;  mrow0 = m0n;
        lrow1 = lrow1 * c1 + rs1;  mrow1 = m1n;
        #pragma unroll
        for (int nf = 0; nf < 8; ++nf) {
            oacc[nf][0] *= c0; oacc[nf][1] *= c0;
            oacc[nf][2] *= c1; oacc[nf][3] *= c1;
        }

        #pragma unroll
        for (int ks2 = 0; ks2 < 8; ++ks2) {
            uint32_t aP[4];
            aP[0] = packh2(sacc[2 * ks2][0],     sacc[2 * ks2][1]);
            aP[1] = packh2(sacc[2 * ks2][2],     sacc[2 * ks2][3]);
            aP[2] = packh2(sacc[2 * ks2 + 1][0], sacc[2 * ks2 + 1][1]);
            aP[3] = packh2(sacc[2 * ks2 + 1][2], sacc[2 * ks2 + 1][3]);
            #pragma unroll
            for (int nb = 0; nb < 4; ++nb) {
                const uint32_t voff =
                    (uint32_t)(((ks2 << 4) + la) * A_STR + (nb << 4) + lk8) * 2;
                uint32_t vbh[4], vbl[4];
                ldm_x4t(vbh, kb_base + A_VH * 2 + voff);
                ldm_x4t(vbl, kb_base + A_VL * 2 + voff);
                mma_f16(oacc[2 * nb],     aP, vbh[0], vbh[1]);
                mma_f16(oacc[2 * nb + 1], aP, vbh[2], vbh[3]);
                mma_f16(oacc[2 * nb],     aP, vbl[0], vbl[1]);
                mma_f16(oacc[2 * nb + 1], aP, vbl[2], vbl[3]);
            }
        }
    }

    const int g  = l >> 2;
    const int tq = (l & 3) << 1;
    const float inv0 = 1.f / lrow0, inv1 = 1.f / lrow1;
    const size_t tok0 = (size_t)b * SEQ + qt * 128 + qrow0 + g;
    #pragma unroll
    for (int nf = 0; nf < 8; ++nf) {
        const int col = h * HDIM + nf * 8 + tq;
        *(uint32_t*)((char*)outh + (tok0 * DMODEL + col) * 2) =
            packh2(oacc[nf][0] * inv0, oacc[nf][1] * inv0);
        *(uint32_t*)((char*)outh + ((tok0 + 8) * DMODEL + col) * 2) =
            packh2(oacc[nf][2] * inv1, oacc[nf][3] * inv1);
    }
}

// =====================================================================
// Fused residual add + LayerNorm; optionally emits fp16 too.
// =====================================================================
template<bool EMIT>
__global__ __launch_bounds__(256)
void add_ln_kernel(const float* __restrict__ a, const float* __restrict__ res,
                   const float* __restrict__ gamma, const float* __restrict__ beta,
                   float* __restrict__ out,
                   __half* __restrict__ outh)
{
    __shared__ float ss[8], qq[8];
    const int row = blockIdx.x;
    const int tid = threadIdx.x;
    const size_t base = (size_t)row * DMODEL + tid * 4;

    float4 va = *(const float4*)&a[base];
    float4 vr = *(const float4*)&res[base];
    float x0 = va.x + vr.x, x1 = va.y + vr.y, x2 = va.z + vr.z, x3 = va.w + vr.w;

    float s = x0 + x1 + x2 + x3;
    float q = x0 * x0 + x1 * x1 + x2 * x2 + x3 * x3;
    #pragma unroll
    for (int off = 16; off > 0; off >>= 1) {
        s += __shfl_xor_sync(0xffffffffu, s, off);
        q += __shfl_xor_sync(0xffffffffu, q, off);
    }
    const int w = tid >> 5;
    if ((tid & 31) == 0) { ss[w] = s; qq[w] = q; }
    __syncthreads();
    if (tid < 32) {
        float s2 = (tid < 8) ? ss[tid] : 0.f;
        float q2 = (tid < 8) ? qq[tid] : 0.f;
        #pragma unroll
        for (int off = 4; off > 0; off >>= 1) {
            s2 += __shfl_xor_sync(0xffffffffu, s2, off);
            q2 += __shfl_xor_sync(0xffffffffu, q2, off);
        }
        if (tid == 0) { ss[0] = s2; qq[0] = q2; }
    }
    __syncthreads();

    const float mean = ss[0] * (1.f / DMODEL);
    const float var  = qq[0] * (1.f / DMODEL) - mean * mean;
    const float rstd = rsqrtf(var + 1e-5f);

    float4 g  = *(const float4*)&gamma[tid * 4];
    float4 bt = *(const float4*)&beta[tid * 4];
    float4 ov;
    ov.x = (x0 - mean) * rstd * g.x + bt.x;
    ov.y = (x1 - mean) * rstd * g.y + bt.y;
    ov.z = (x2 - mean) * rstd * g.z + bt.z;
    ov.w = (x3 - mean) * rstd * g.w + bt.w;
    *(float4*)&out[base] = ov;

    if (EMIT) {
        *(uint2*)((char*)outh + base * 2) =
            make_uint2(packh2(ov.x, ov.y), packh2(ov.z, ov.w));
    }
}

// =====================================================================
// kernel_launch
// =====================================================================
extern "C" void kernel_launch(void* const* d_in, const int* in_sizes, int n_in,
                              void* d_out, int out_size)
{
    const float* x      = (const float*)d_in[0];
    const float* W_qkv  = (const float*)d_in[1];
    const float* b_qkv  = (const float*)d_in[2];
    const float* W_o    = (const float*)d_in[3];
    const float* b_o    = (const float*)d_in[4];
    const float* gamma1 = (const float*)d_in[5];
    const float* beta1  = (const float*)d_in[6];
    const float* W1     = (const float*)d_in[7];
    const float* b1     = (const float*)d_in[8];
    const float* W2     = (const float*)d_in[9];
    const float* b2     = (const float*)d_in[10];
    const float* gamma2 = (const float*)d_in[11];
    const float* beta2  = (const float*)d_in[12];
    float* out = (float*)d_out;

    float *qkv, *attnout, *h1, *ffn2;
    cudaGetSymbolAddress((void**)&qkv,     g_qkv);
    cudaGetSymbolAddress((void**)&attnout, g_attnout);
    cudaGetSymbolAddress((void**)&h1,      g_h1);
    cudaGetSymbolAddress((void**)&ffn2,    g_ffn2);

    __half *xh, *wqh, *woh, *w1h, *w2h;
    __half *ath, *h1h, *fhh;
    __half *qph, *qpl, *kph, *vph, *vpl;
    cudaGetSymbolAddress((void**)&xh,  g_xh);
    cudaGetSymbolAddress((void**)&wqh, g_wqt_h);
    cudaGetSymbolAddress((void**)&woh, g_wot_h);
    cudaGetSymbolAddress((void**)&w1h, g_w1t_h);
    cudaGetSymbolAddress((void**)&w2h, g_w2t_h);
    cudaGetSymbolAddress((void**)&ath, g_attnh);
    cudaGetSymbolAddress((void**)&h1h, g_h1h);
    cudaGetSymbolAddress((void**)&fhh, g_fhh);
    cudaGetSymbolAddress((void**)&qph, g_qph);  cudaGetSymbolAddress((void**)&qpl, g_qpl);
    cudaGetSymbolAddress((void**)&kph, g_kph);
    cudaGetSymbolAddress((void**)&vph, g_vph);  cudaGetSymbolAddress((void**)&vpl, g_vpl);

    cudaFuncSetAttribute(attention_mma,
                         cudaFuncAttributeMaxDynamicSharedMemorySize, ATTN_SMEM);
    cudaFuncSetAttribute(gemm_f16<false, false>,
                         cudaFuncAttributeMaxDynamicSharedMemorySize, GEMM_SMEM);
    cudaFuncSetAttribute(gemm_f16<false, true>,
                         cudaFuncAttributeMaxDynamicSharedMemorySize, GEMM_SMEM);
    cudaFuncSetAttribute(gemm_f16<true, true>,
                         cudaFuncAttributeMaxDynamicSharedMemorySize, GEMM_SMEM);

    dim3 blk(256);

    // ---- one-time converts ----
    conv_plain<<<(TOKENS * DMODEL) / (256 * 4), blk>>>(x, xh);
    conv_transpose<<<dim3(D3 / 32,    DMODEL / 32), blk>>>(W_qkv, wqh, DMODEL, D3);
    conv_transpose<<<dim3(DMODEL / 32, DMODEL / 32), blk>>>(W_o,  woh, DMODEL, DMODEL);
    conv_transpose<<<dim3(FFN / 32,   DMODEL / 32), blk>>>(W1,   w1h, DMODEL, FFN);
    conv_transpose<<<dim3(DMODEL / 32, FFN / 32),   blk>>>(W2,   w2h, FFN, DMODEL);

    // 1) qkv = x @ W_qkv + b_qkv                       [4096, 3072]
    gemm_f16<false, false><<<dim3(D3 / 128, TOKENS / 128), blk, GEMM_SMEM>>>(
        xh, wqh, b_qkv, qkv, nullptr, TOKENS, D3, DMODEL);

    // 1b) split qkv -> per-head planar fp16 (Q pre-scaled)
    split_qkv<<<(TOKENS * D3) / (256 * 4), blk>>>(qkv, qph, qpl, kph, vph, vpl);

    // 2) MMA flash attention -> fp16                   [4096, 1024]
    attention_mma<<<dim3(SEQ / 128, BATCH * NHEAD), blk, ATTN_SMEM>>>(
        qph, qpl, kph, vph, vpl, ath);

    // 3) attn_out = attn @ W_o + b_o                   [4096, 1024]
    gemm_f16<false, false><<<dim3(DMODEL / 128, TOKENS / 128), blk, GEMM_SMEM>>>(
        ath, woh, b_o, attnout, nullptr, TOKENS, DMODEL, DMODEL);

    // 4) h1 = LN(attn_out + x)  (+ fp16)
    add_ln_kernel<true><<<TOKENS, blk>>>(attnout, x, gamma1, beta1, h1, h1h);

    // 5) ffnh = relu(h1 @ W1 + b1) -> fp16             [4096, 4096]
    gemm_f16<true, true><<<dim3(FFN / 128, TOKENS / 128), blk, GEMM_SMEM>>>(
        h1h, w1h, b1, nullptr, fhh, TOKENS, FFN, DMODEL);

    // 6) ffn2 = ffnh @ W2 + b2                         [4096, 1024]
    gemm_f16<false, false><<<dim3(DMODEL / 128, TOKENS / 128), blk, GEMM_SMEM>>>(
        fhh, w2h, b2, ffn2, nullptr, TOKENS, DMODEL, FFN);

    // 7) out = LN(ffn2 + h1)
    add_ln_kernel<false><<<TOKENS, blk>>>(ffn2, h1, gamma2, beta2, out, nullptr);
}

// round 10
// speedup vs baseline: 3.1442x; 1.0205x over previous
#include <cuda_runtime.h>
#include <cuda_fp16.h>
#include <cstdint>
#include <math.h>

// ---------------- problem constants ----------------
#define TOKENS 4096          // B*S = 2*2048
#define SEQ    2048
#define BATCH  2
#define DMODEL 1024
#define D3     3072
#define FFN    4096
#define NHEAD  16
#define HDIM   64

// ---------------- fp32 scratch ----------------
__device__ float g_attnout[TOKENS * (size_t)DMODEL];
__device__ float g_h1     [TOKENS * (size_t)DMODEL];
__device__ float g_ffn2   [TOKENS * (size_t)DMODEL];

// ---------------- fp16 scratch ----------------
__device__ __half g_xh   [TOKENS * (size_t)DMODEL];
__device__ __half g_wqt_h[(size_t)D3 * DMODEL];     // [N][K]
__device__ __half g_wot_h[(size_t)DMODEL * DMODEL];
__device__ __half g_w1t_h[(size_t)FFN * DMODEL];
__device__ __half g_w2t_h[(size_t)DMODEL * FFN];
__device__ __half g_attnh[TOKENS * (size_t)DMODEL];
__device__ __half g_h1h  [TOKENS * (size_t)DMODEL];
__device__ __half g_fhh  [TOKENS * (size_t)FFN];

// ---------------- per-head planar fp16 QKV ----------
// layout: [bh][seq][64]
__device__ __half g_qph[(size_t)BATCH * NHEAD * SEQ * HDIM];
__device__ __half g_qpl[(size_t)BATCH * NHEAD * SEQ * HDIM];
__device__ __half g_kph[(size_t)BATCH * NHEAD * SEQ * HDIM];
__device__ __half g_vph[(size_t)BATCH * NHEAD * SEQ * HDIM];
__device__ __half g_vpl[(size_t)BATCH * NHEAD * SEQ * HDIM];

// =====================================================================
// helpers
// =====================================================================
__device__ __forceinline__ uint32_t smem_u32(const void* p) {
    uint32_t a;
    asm("{ .reg .u64 t; cvta.to.shared.u64 t, %1; cvt.u32.u64 %0, t; }"
        : "=r"(a) : "l"(p));
    return a;
}

__device__ __forceinline__ void ldm_x4(uint32_t* r, uint32_t addr) {
    asm volatile("ldmatrix.sync.aligned.m8n8.x4.shared.b16 {%0,%1,%2,%3}, [%4];"
                 : "=r"(r[0]), "=r"(r[1]), "=r"(r[2]), "=r"(r[3]) : "r"(addr));
}

__device__ __forceinline__ void ldm_x4t(uint32_t* r, uint32_t addr) {
    asm volatile("ldmatrix.sync.aligned.m8n8.x4.trans.shared.b16 {%0,%1,%2,%3}, [%4];"
                 : "=r"(r[0]), "=r"(r[1]), "=r"(r[2]), "=r"(r[3]) : "r"(addr));
}

__device__ __forceinline__ void mma_f16(float* d, const uint32_t* a,
                                        uint32_t b0, uint32_t b1) {
    asm volatile(
        "mma.sync.aligned.m16n8k16.row.col.f32.f16.f16.f32 "
        "{%0,%1,%2,%3},{%4,%5,%6,%7},{%8,%9},{%0,%1,%2,%3};"
        : "+f"(d[0]), "+f"(d[1]), "+f"(d[2]), "+f"(d[3])
        : "r"(a[0]), "r"(a[1]), "r"(a[2]), "r"(a[3]), "r"(b0), "r"(b1));
}

__device__ __forceinline__ uint32_t packh2(float a, float b) {
    __half2 h = __floats2half2_rn(a, b);
    return *reinterpret_cast<uint32_t*>(&h);
}

// split pair into fp16-rn hi pair and fp16-rn residual-lo pair
__device__ __forceinline__ void split2h(float x, float y,
                                        uint32_t& hi, uint32_t& lo) {
    __half2 h = __floats2half2_rn(x, y);
    hi = *reinterpret_cast<uint32_t*>(&h);
    float rx = x - __half2float(__low2half(h));
    float ry = y - __half2float(__high2half(h));
    __half2 l = __floats2half2_rn(rx, ry);
    lo = *reinterpret_cast<uint32_t*>(&l);
}

__device__ __forceinline__ void cp16(uint32_t dst, const void* src) {
    asm volatile("cp.async.cg.shared.global [%0], [%1], 16;"
                 :: "r"(dst), "l"(src));
}
#define CP_COMMIT() asm volatile("cp.async.commit_group;" ::: "memory")
#define CP_WAIT0()  asm volatile("cp.async.wait_group 0;" ::: "memory")

// fused QKV epilogue writer: (row, col pair) of qkv fp32 -> planar fp16
__device__ __forceinline__ void qkv_write(
    __half* __restrict__ qh, __half* __restrict__ ql,
    __half* __restrict__ kh,
    __half* __restrict__ vh, __half* __restrict__ vl,
    int row, int col, float x, float y)
{
    const int h    = col / 192;
    const int r2   = col - h * 192;
    const int part = r2 >> 6;            // 0=q 1=k 2=v
    const int d    = r2 & 63;            // even (col pairs are even)
    const int b    = row >> 11, s = row & 2047;
    const size_t po = ((size_t)(b * NHEAD + h) * SEQ + s) * HDIM + d;
    if (part == 0) {
        uint32_t hi, lo;
        split2h(x * 0.125f, y * 0.125f, hi, lo);
        *(uint32_t*)(qh + po) = hi;
        *(uint32_t*)(ql + po) = lo;
    } else if (part == 1) {
        *(uint32_t*)(kh + po) = packh2(x, y);
    } else {
        uint32_t hi, lo;
        split2h(x, y, hi, lo);
        *(uint32_t*)(vh + po) = hi;
        *(uint32_t*)(vl + po) = lo;
    }
}

// =====================================================================
// convert kernels (run once per launch; memory-bound)
// =====================================================================
__global__ __launch_bounds__(256)
void conv_plain(const float* __restrict__ src, __half* __restrict__ dh)
{
    const int idx = blockIdx.x * 256 + threadIdx.x;     // float4 index
    float4 v = ((const float4*)src)[idx];
    ((uint2*)dh)[idx] = make_uint2(packh2(v.x, v.y), packh2(v.z, v.w));
}

// W[K][N] -> Th[N][K] (fp16-rn)
__global__ __launch_bounds__(256)
void conv_transpose(const float* __restrict__ W,
                    __half* __restrict__ Th, int K, int N)
{
    __shared__ float t[32][33];
    const int bn = blockIdx.x * 32, bk = blockIdx.y * 32;
    const int tx = threadIdx.x & 31, ty = threadIdx.x >> 5;   // 32 x 8
    #pragma unroll
    for (int j = 0; j < 32; j += 8)
        t[ty + j][tx] = W[(size_t)(bk + ty + j) * N + bn + tx];
    __syncthreads();
    #pragma unroll
    for (int j = 0; j < 32; j += 8) {
        size_t o = (size_t)(bn + ty + j) * K + bk + tx;
        Th[o] = __float2half_rn(t[tx][ty + j]);
    }
}

// =====================================================================
// HMMA GEMM, pure fp16: C = A @ B^T + bias.
// A: [M][K] fp16.  B: [N][K] fp16.
// CTA 128x128, BK=64 (2x 32-k sub-tiles), 8 warps (warp tile 64x32),
// cp.async double buffer, 2 CTAs/SM.
// MODE: 0 = fp32 out, 1 = relu + fp16 out, 2 = fused QKV planar out.
// =====================================================================
#define STRB   80                     // bytes per smem row (32 fp16 + pad)
#define TILE32 (128 * STRB)           // 10240 B per 128x32 tile
#define BUF_B  (4 * TILE32)           // A0, A1, B0, B1 = 40960 B
#define GEMM_SMEM (2 * BUF_B)         // 81920 B

template<int MODE>
__global__ __launch_bounds__(256, 2)
void gemm_f16(const __half* __restrict__ Ah,
              const __half* __restrict__ Bh,
              const float* __restrict__ bias,
              float* __restrict__ C,
              __half* __restrict__ Ch,
              __half* __restrict__ qh, __half* __restrict__ ql,
              __half* __restrict__ kh,
              __half* __restrict__ vh, __half* __restrict__ vl,
              int M, int N, int K)
{
    extern __shared__ char smraw[];
    const uint32_t sb = smem_u32(smraw);
    const int tid = threadIdx.x;
    const int l   = tid & 31, w = tid >> 5;
    const int bm  = blockIdx.y * 128, bn = blockIdx.x * 128;
    const int wm  = (w & 1) << 6;
    const int wn  = (w >> 1) << 5;

    const int la = l & 15;
    const int lk = (l >> 4) << 3;
    const int T  = K >> 6;

    float acc[4][4][4];
    #pragma unroll
    for (int i = 0; i < 4; ++i)
        #pragma unroll
        for (int j = 0; j < 4; ++j)
            #pragma unroll
            for (int q = 0; q < 4; ++q) acc[i][j][q] = 0.f;

    auto issue_tile = [&](int t) {
        const int k0 = t << 6;
        const uint32_t base = sb + (t & 1) * BUF_B;
        #pragma unroll
        for (int s32 = 0; s32 < 2; ++s32)
            #pragma unroll
            for (int i = 0; i < 2; ++i) {
                const int c   = tid + (i << 8);     // 0..511
                const int row = c >> 2, kc = c & 3;
                const uint32_t doff = (uint32_t)(row * STRB + kc * 16);
                const int kg = k0 + s32 * 32 + kc * 8;
                cp16(base + s32 * TILE32 + doff,
                     Ah + (size_t)(bm + row) * K + kg);
                cp16(base + 2 * TILE32 + s32 * TILE32 + doff,
                     Bh + (size_t)(bn + row) * K + kg);
            }
        CP_COMMIT();
    };

    auto compute = [&](int bsel) {
        const uint32_t base0 = sb + bsel * BUF_B;
        #pragma unroll
        for (int s32 = 0; s32 < 2; ++s32) {
            const uint32_t baseA = base0 + s32 * TILE32;
            const uint32_t baseB = base0 + 2 * TILE32 + s32 * TILE32;
            #pragma unroll
            for (int ks = 0; ks < 2; ++ks) {
                uint32_t ah[4][4], bh[2][4];
                #pragma unroll
                for (int mf = 0; mf < 4; ++mf) {
                    uint32_t off = (uint32_t)((wm + mf * 16 + la) * STRB +
                                              (ks * 16 + lk) * 2);
                    ldm_x4(ah[mf], baseA + off);
                }
                #pragma unroll
                for (int nf2 = 0; nf2 < 2; ++nf2) {
                    uint32_t off = (uint32_t)((wn + nf2 * 16 + la) * STRB +
                                              (ks * 16 + lk) * 2);
                    ldm_x4(bh[nf2], baseB + off);
                }
                #pragma unroll
                for (int mf = 0; mf < 4; ++mf)
                    #pragma unroll
                    for (int nf = 0; nf < 4; ++nf) {
                        const int g = nf >> 1, s = nf & 1;
                        mma_f16(acc[mf][nf], ah[mf], bh[g][s], bh[g][2 + s]);
                    }
            }
        }
    };

    issue_tile(0);
    for (int t = 0; t < T; ++t) {
        CP_WAIT0();
        __syncthreads();
        if (t + 1 < T) issue_tile(t + 1);
        compute(t & 1);
        __syncthreads();
    }

    const int g  = l >> 2;
    const int tg = (l & 3) << 1;
    #pragma unroll
    for (int mf = 0; mf < 4; ++mf) {
        const int r0 = bm + wm + mf * 16 + g;
        #pragma unroll
        for (int nf = 0; nf < 4; ++nf) {
            const int c = bn + wn + nf * 8 + tg;
            float2 bv = *(const float2*)&bias[c];
            float v0 = acc[mf][nf][0] + bv.x;
            float v1 = acc[mf][nf][1] + bv.y;
            float v2 = acc[mf][nf][2] + bv.x;
            float v3 = acc[mf][nf][3] + bv.y;
            if (MODE == 1) {
                v0 = fmaxf(v0, 0.f); v1 = fmaxf(v1, 0.f);
                v2 = fmaxf(v2, 0.f); v3 = fmaxf(v3, 0.f);
                *(uint32_t*)((char*)Ch + ((size_t)r0 * N + c) * 2)       = packh2(v0, v1);
                *(uint32_t*)((char*)Ch + ((size_t)(r0 + 8) * N + c) * 2) = packh2(v2, v3);
            } else if (MODE == 2) {
                qkv_write(qh, ql, kh, vh, vl, r0,     c, v0, v1);
                qkv_write(qh, ql, kh, vh, vl, r0 + 8, c, v2, v3);
            } else {
                *(float2*)&C[(size_t)r0 * N + c]       = make_float2(v0, v1);
                *(float2*)&C[(size_t)(r0 + 8) * N + c] = make_float2(v2, v3);
            }
        }
    }
}

// =====================================================================
// MMA flash attention (proven; unchanged).
// grid (16 qtiles, 32 bh), 256 threads (8 warps), warp = 16 q-rows.
// =====================================================================
#define A_STR   72                         // halves per smem row (64 + 8 pad)
#define A_TILE  (128 * A_STR)              // 9216 halves per tile
#define A_QH    0
#define A_QL    A_TILE
#define A_BUF0  (2 * A_TILE)               // 18432
#define A_BUFSZ (3 * A_TILE)               // Kh, Vh, Vl = 27648 halves
#define A_KH    0
#define A_VH    A_TILE
#define A_VL    (2 * A_TILE)
#define ATTN_SMEM ((A_BUF0 + 2 * A_BUFSZ) * 2)   // 147456 bytes

__global__ __launch_bounds__(256, 1)
void attention_mma(const __half* __restrict__ qh_g, const __half* __restrict__ ql_g,
                   const __half* __restrict__ kh_g,
                   const __half* __restrict__ vh_g, const __half* __restrict__ vl_g,
                   __half* __restrict__ outh)
{
    extern __shared__ char smraw[];
    const uint32_t sb = smem_u32(smraw);
    const int tid = threadIdx.x;
    const int l   = tid & 31, w = tid >> 5;
    const int qt  = blockIdx.x;
    const int bh  = blockIdx.y;
    const int b   = bh >> 4, h = bh & 15;

    const size_t plane = (size_t)bh * SEQ * HDIM;
    const int la  = l & 15;
    const int lk8 = (l >> 4) << 3;
    const int qrow0 = w << 4;

    auto load_tile = [&](const __half* src, uint32_t dsth, int row0) {
        #pragma unroll
        for (int i = 0; i < 4; ++i) {
            const int c   = tid + (i << 8);        // 0..1023
            const int row = c >> 3, c8 = (c & 7) << 3;
            cp16(sb + (dsth + row * A_STR + c8) * 2,
                 src + plane + (size_t)(row0 + row) * HDIM + c8);
        }
    };

    load_tile(qh_g, A_QH, qt * 128);
    load_tile(ql_g, A_QL, qt * 128);
    load_tile(kh_g, A_BUF0 + A_KH, 0);
    load_tile(vh_g, A_BUF0 + A_VH, 0);
    load_tile(vl_g, A_BUF0 + A_VL, 0);
    CP_COMMIT();

    float oacc[8][4];
    #pragma unroll
    for (int i = 0; i < 8; ++i)
        #pragma unroll
        for (int j = 0; j < 4; ++j) oacc[i][j] = 0.f;
    float mrow0 = -1e30f, mrow1 = -1e30f, lrow0 = 0.f, lrow1 = 0.f;

    for (int kt = 0; kt < SEQ / 128; ++kt) {
        CP_WAIT0();
        __syncthreads();
        if (kt + 1 < SEQ / 128) {
            const uint32_t nb = A_BUF0 + ((kt + 1) & 1) * A_BUFSZ;
            load_tile(kh_g, nb + A_KH, (kt + 1) * 128);
            load_tile(vh_g, nb + A_VH, (kt + 1) * 128);
            load_tile(vl_g, nb + A_VL, (kt + 1) * 128);
            CP_COMMIT();
        }
        const uint32_t kb_base = sb + (A_BUF0 + (kt & 1) * A_BUFSZ) * 2;

        float sacc[16][4];
        #pragma unroll
        for (int i = 0; i < 16; ++i)
            #pragma unroll
            for (int j = 0; j < 4; ++j) sacc[i][j] = 0.f;

        #pragma unroll
        for (int ks = 0; ks < 4; ++ks) {
            const uint32_t qoff = (uint32_t)((qrow0 + la) * A_STR + ks * 16 + lk8) * 2;
            uint32_t qhf[4], qlf[4];
            ldm_x4(qhf, sb + A_QH * 2 + qoff);
            ldm_x4(qlf, sb + A_QL * 2 + qoff);
            uint32_t kb[8][4];
            #pragma unroll
            for (int g2 = 0; g2 < 8; ++g2)
                ldm_x4(kb[g2], kb_base +
                       (uint32_t)(((g2 << 4) + la) * A_STR + ks * 16 + lk8) * 2);
            #pragma unroll
            for (int nf = 0; nf < 16; ++nf) {
                const int g2 = nf >> 1, s = nf & 1;
                mma_f16(sacc[nf], qhf, kb[g2][s], kb[g2][2 + s]);
                mma_f16(sacc[nf], qlf, kb[g2][s], kb[g2][2 + s]);
            }
        }

        float tm0 = -1e30f, tm1 = -1e30f;
        #pragma unroll
        for (int nf = 0; nf < 16; ++nf) {
            tm0 = fmaxf(tm0, fmaxf(sacc[nf][0], sacc[nf][1]));
            tm1 = fmaxf(tm1, fmaxf(sacc[nf][2], sacc[nf][3]));
        }
        tm0 = fmaxf(tm0, __shfl_xor_sync(0xffffffffu, tm0, 1));
        tm0 = fmaxf(tm0, __shfl_xor_sync(0xffffffffu, tm0, 2));
        tm1 = fmaxf(tm1, __shfl_xor_sync(0xffffffffu, tm1, 1));
        tm1 = fmaxf(tm1, __shfl_xor_sync(0xffffffffu, tm1, 2));
        const float m0n = fmaxf(mrow0, tm0), m1n = fmaxf(mrow1, tm1);
        const float c0 = __expf(mrow0 - m0n), c1 = __expf(mrow1 - m1n);
        float rs0 = 0.f, rs1 = 0.f;
        #pragma unroll
        for (int nf = 0; nf < 16; ++nf) {
            sacc[nf][0] = __expf(sacc[nf][0] - m0n);
            sacc[nf][1] = __expf(sacc[nf][1] - m0n);
            sacc[nf][2] = __expf(sacc[nf][2] - m1n);
            sacc[nf][3] = __expf(sacc[nf][3] - m1n);
            rs0 += sacc[nf][0] + sacc[nf][1];
            rs1 += sacc[nf][2] + sacc[nf][3];
        }
        rs0 += __shfl_xor_sync(0xffffffffu, rs0, 1);
        rs0 += __shfl_xor_sync(0xffffffffu, rs0, 2);
        rs1 += __shfl_xor_sync(0xffffffffu, rs1, 1);
        rs1 += __shfl_xor_sync(0xffffffffu, rs1, 2);
        lrow0 = lrow0 * c0 + rs0;  mrow0 = m0n;
        lrow1 = lrow1 * c1 + rs1;  mrow1 = m1n;
        #pragma unroll
        for (int nf = 0; nf < 8; ++nf) {
            oacc[nf][0] *= c0; oacc[nf][1] *= c0;
            oacc[nf][2] *= c1; oacc[nf][3] *= c1;
        }

        #pragma unroll
        for (int ks2 = 0; ks2 < 8; ++ks2) {
            uint32_t aP[4];
            aP[0] = packh2(sacc[2 * ks2][0],     sacc[2 * ks2][1]);
            aP[1] = packh2(sacc[2 * ks2][2],     sacc[2 * ks2][3]);
            aP[2] = packh2(sacc[2 * ks2 + 1][0], sacc[2 * ks2 + 1][1]);
            aP[3] = packh2(sacc[2 * ks2 + 1][2], sacc[2 * ks2 + 1][3]);
            #pragma unroll
            for (int nb = 0; nb < 4; ++nb) {
                const uint32_t voff =
                    (uint32_t)(((ks2 << 4) + la) * A_STR + (nb << 4) + lk8) * 2;
                uint32_t vbh[4], vbl[4];
                ldm_x4t(vbh, kb_base + A_VH * 2 + voff);
                ldm_x4t(vbl, kb_base + A_VL * 2 + voff);
                mma_f16(oacc[2 * nb],     aP, vbh[0], vbh[1]);
                mma_f16(oacc[2 * nb + 1], aP, vbh[2], vbh[3]);
                mma_f16(oacc[2 * nb],     aP, vbl[0], vbl[1]);
                mma_f16(oacc[2 * nb + 1], aP, vbl[2], vbl[3]);
            }
        }
    }

    const int g  = l >> 2;
    const int tq = (l & 3) << 1;
    const float inv0 = 1.f / lrow0, inv1 = 1.f / lrow1;
    const size_t tok0 = (size_t)b * SEQ + qt * 128 + qrow0 + g;
    #pragma unroll
    for (int nf = 0; nf < 8; ++nf) {
        const int col = h * HDIM + nf * 8 + tq;
        *(uint32_t*)((char*)outh + (tok0 * DMODEL + col) * 2) =
            packh2(oacc[nf][0] * inv0, oacc[nf][1] * inv0);
        *(uint32_t*)((char*)outh + ((tok0 + 8) * DMODEL + col) * 2) =
            packh2(oacc[nf][2] * inv1, oacc[nf][3] * inv1);
    }
}

// =====================================================================
// Fused residual add + LayerNorm; optionally emits fp16 too.
// =====================================================================
template<bool EMIT>
__global__ __launch_bounds__(256)
void add_ln_kernel(const float* __restrict__ a, const float* __restrict__ res,
                   const float* __restrict__ gamma, const float* __restrict__ beta,
                   float* __restrict__ out,
                   __half* __restrict__ outh)
{
    __shared__ float ss[8], qq[8];
    const int row = blockIdx.x;
    const int tid = threadIdx.x;
    const size_t base = (size_t)row * DMODEL + tid * 4;

    float4 va = *(const float4*)&a[base];
    float4 vr = *(const float4*)&res[base];
    float x0 = va.x + vr.x, x1 = va.y + vr.y, x2 = va.z + vr.z, x3 = va.w + vr.w;

    float s = x0 + x1 + x2 + x3;
    float q = x0 * x0 + x1 * x1 + x2 * x2 + x3 * x3;
    #pragma unroll
    for (int off = 16; off > 0; off >>= 1) {
        s += __shfl_xor_sync(0xffffffffu, s, off);
        q += __shfl_xor_sync(0xffffffffu, q, off);
    }
    const int w = tid >> 5;
    if ((tid & 31) == 0) { ss[w] = s; qq[w] = q; }
    __syncthreads();
    if (tid < 32) {
        float s2 = (tid < 8) ? ss[tid] : 0.f;
        float q2 = (tid < 8) ? qq[tid] : 0.f;
        #pragma unroll
        for (int off = 4; off > 0; off >>= 1) {
            s2 += __shfl_xor_sync(0xffffffffu, s2, off);
            q2 += __shfl_xor_sync(0xffffffffu, q2, off);
        }
        if (tid == 0) { ss[0] = s2; qq[0] = q2; }
    }
    __syncthreads();

    const float mean = ss[0] * (1.f / DMODEL);
    const float var  = qq[0] * (1.f / DMODEL) - mean * mean;
    const float rstd = rsqrtf(var + 1e-5f);

    float4 g  = *(const float4*)&gamma[tid * 4];
    float4 bt = *(const float4*)&beta[tid * 4];
    float4 ov;
    ov.x = (x0 - mean) * rstd * g.x + bt.x;
    ov.y = (x1 - mean) * rstd * g.y + bt.y;
    ov.z = (x2 - mean) * rstd * g.z + bt.z;
    ov.w = (x3 - mean) * rstd * g.w + bt.w;
    *(float4*)&out[base] = ov;

    if (EMIT) {
        *(uint2*)((char*)outh + base * 2) =
            make_uint2(packh2(ov.x, ov.y), packh2(ov.z, ov.w));
    }
}

// =====================================================================
// kernel_launch
// =====================================================================
extern "C" void kernel_launch(void* const* d_in, const int* in_sizes, int n_in,
                              void* d_out, int out_size)
{
    const float* x      = (const float*)d_in[0];
    const float* W_qkv  = (const float*)d_in[1];
    const float* b_qkv  = (const float*)d_in[2];
    const float* W_o    = (const float*)d_in[3];
    const float* b_o    = (const float*)d_in[4];
    const float* gamma1 = (const float*)d_in[5];
    const float* beta1  = (const float*)d_in[6];
    const float* W1     = (const float*)d_in[7];
    const float* b1     = (const float*)d_in[8];
    const float* W2     = (const float*)d_in[9];
    const float* b2     = (const float*)d_in[10];
    const float* gamma2 = (const float*)d_in[11];
    const float* beta2  = (const float*)d_in[12];
    float* out = (float*)d_out;

    float *attnout, *h1, *ffn2;
    cudaGetSymbolAddress((void**)&attnout, g_attnout);
    cudaGetSymbolAddress((void**)&h1,      g_h1);
    cudaGetSymbolAddress((void**)&ffn2,    g_ffn2);

    __half *xh, *wqh, *woh, *w1h, *w2h;
    __half *ath, *h1h, *fhh;
    __half *qph, *qpl, *kph, *vph, *vpl;
    cudaGetSymbolAddress((void**)&xh,  g_xh);
    cudaGetSymbolAddress((void**)&wqh, g_wqt_h);
    cudaGetSymbolAddress((void**)&woh, g_wot_h);
    cudaGetSymbolAddress((void**)&w1h, g_w1t_h);
    cudaGetSymbolAddress((void**)&w2h, g_w2t_h);
    cudaGetSymbolAddress((void**)&ath, g_attnh);
    cudaGetSymbolAddress((void**)&h1h, g_h1h);
    cudaGetSymbolAddress((void**)&fhh, g_fhh);
    cudaGetSymbolAddress((void**)&qph, g_qph);  cudaGetSymbolAddress((void**)&qpl, g_qpl);
    cudaGetSymbolAddress((void**)&kph, g_kph);
    cudaGetSymbolAddress((void**)&vph, g_vph);  cudaGetSymbolAddress((void**)&vpl, g_vpl);

    cudaFuncSetAttribute(attention_mma,
                         cudaFuncAttributeMaxDynamicSharedMemorySize, ATTN_SMEM);
    cudaFuncSetAttribute(gemm_f16<0>,
                         cudaFuncAttributeMaxDynamicSharedMemorySize, GEMM_SMEM);
    cudaFuncSetAttribute(gemm_f16<1>,
                         cudaFuncAttributeMaxDynamicSharedMemorySize, GEMM_SMEM);
    cudaFuncSetAttribute(gemm_f16<2>,
                         cudaFuncAttributeMaxDynamicSharedMemorySize, GEMM_SMEM);

    dim3 blk(256);

    // ---- one-time converts ----
    conv_plain<<<(TOKENS * DMODEL) / (256 * 4), blk>>>(x, xh);
    conv_transpose<<<dim3(D3 / 32,    DMODEL / 32), blk>>>(W_qkv, wqh, DMODEL, D3);
    conv_transpose<<<dim3(DMODEL / 32, DMODEL / 32), blk>>>(W_o,  woh, DMODEL, DMODEL);
    conv_transpose<<<dim3(FFN / 32,   DMODEL / 32), blk>>>(W1,   w1h, DMODEL, FFN);
    conv_transpose<<<dim3(DMODEL / 32, FFN / 32),   blk>>>(W2,   w2h, FFN, DMODEL);

    // 1) qkv GEMM with fused planar-QKV epilogue       [4096, 3072]
    gemm_f16<2><<<dim3(D3 / 128, TOKENS / 128), blk, GEMM_SMEM>>>(
        xh, wqh, b_qkv, nullptr, nullptr,
        qph, qpl, kph, vph, vpl, TOKENS, D3, DMODEL);

    // 2) MMA flash attention -> fp16                   [4096, 1024]
    attention_mma<<<dim3(SEQ / 128, BATCH * NHEAD), blk, ATTN_SMEM>>>(
        qph, qpl, kph, vph, vpl, ath);

    // 3) attn_out = attn @ W_o + b_o                   [4096, 1024]
    gemm_f16<0><<<dim3(DMODEL / 128, TOKENS / 128), blk, GEMM_SMEM>>>(
        ath, woh, b_o, attnout, nullptr,
        nullptr, nullptr, nullptr, nullptr, nullptr, TOKENS, DMODEL, DMODEL);

    // 4) h1 = LN(attn_out + x)  (+ fp16)
    add_ln_kernel<true><<<TOKENS, blk>>>(attnout, x, gamma1, beta1, h1, h1h);

    // 5) ffnh = relu(h1 @ W1 + b1) -> fp16             [4096, 4096]
    gemm_f16<1><<<dim3(FFN / 128, TOKENS / 128), blk, GEMM_SMEM>>>(
        h1h, w1h, b1, nullptr, fhh,
        nullptr, nullptr, nullptr, nullptr, nullptr, TOKENS, FFN, DMODEL);

    // 6) ffn2 = ffnh @ W2 + b2                         [4096, 1024]
    gemm_f16<0><<<dim3(DMODEL / 128, TOKENS / 128), blk, GEMM_SMEM>>>(
        fhh, w2h, b2, ffn2, nullptr,
        nullptr, nullptr, nullptr, nullptr, nullptr, TOKENS, DMODEL, FFN);

    // 7) out = LN(ffn2 + h1)
    add_ln_kernel<false><<<TOKENS, blk>>>(ffn2, h1, gamma2, beta2, out, nullptr);
}